// round 6
// baseline (speedup 1.0000x reference)
#include <cuda_runtime.h>
#include <cuda_fp16.h>
#include <cstdint>

// ---------------- problem constants ----------------
#define NPTS 20000
#define MNBR 20
#define ERBF 20
#define HDIM 128
#define BCRY 200
#define NBLK 8
#define PI_F 3.14159265358979f
#define KNOT 4096
#define DMAX_CHE 8.81f
#define DMAX_VDW 13.21f

typedef unsigned long long u64;

// ---------------- device scratch ----------------
__device__ int   g_order;
__device__ float g_nodesA[NPTS * HDIM];
__device__ float g_nodesB[NPTS * HDIM];
__device__ float g_ST[(size_t)NPTS * 1024];        // [S_che|T_che|S_vdw|T_vdw] interleaved (filt,core)
__device__ float g_Wcat[3 * 131072];
__device__ float g_We[3 * 2 * ERBF * 256];
__device__ float g_be[3 * 2 * 256];
__device__ float g_tab[(size_t)3 * 2 * KNOT * 256];      // fp32 scalar table (build stage)
__device__ uint2 g_tab16[(size_t)3 * 2 * KNOT * 128];    // packed fp16: {f_j,c_j,f_j+1,c_j+1} per (j,h)

// ---------------- f32x2 packed math ----------------
__device__ __forceinline__ u64 pk2(float lo, float hi) {
    u64 r; asm("mov.b64 %0, {%1,%2};" : "=l"(r) : "f"(lo), "f"(hi)); return r;
}
__device__ __forceinline__ void upk2(u64 v, float& lo, float& hi) {
    asm("mov.b64 {%0,%1}, %2;" : "=f"(lo), "=f"(hi) : "l"(v));
}
__device__ __forceinline__ u64 fma2(u64 a, u64 b, u64 c) {
    u64 d; asm("fma.rn.f32x2 %0, %1, %2, %3;" : "=l"(d) : "l"(a), "l"(b), "l"(c)); return d;
}
__device__ __forceinline__ u64 add2(u64 a, u64 b) {
    u64 d; asm("add.rn.f32x2 %0, %1, %2;" : "=l"(d) : "l"(a), "l"(b)); return d;
}
__device__ __forceinline__ u64 mul2(u64 a, u64 b) {
    u64 d; asm("mul.rn.f32x2 %0, %1, %2;" : "=l"(d) : "l"(a), "l"(b)); return d;
}

// ---------------- activations ----------------
__device__ __forceinline__ float softplusf_(float x) {
    return fmaxf(x, 0.f) + __logf(1.f + __expf(-fabsf(x)));
}
__device__ __forceinline__ float gatef_(float f, float c) {
    float sig = __fdividef(1.f, 1.f + __expf(-f));
    return sig * softplusf_(c);
}

// ---------------- 1: merged prep: detect + folded edge weights + Wcat ----------------
__global__ __launch_bounds__(256) void prep_kernel(
    const unsigned* __restrict__ p2u,
    const float* __restrict__ cheFW, const float* __restrict__ cheFb,
    const float* __restrict__ cheGW, const float* __restrict__ cheGb,
    const float* __restrict__ vdwFW, const float* __restrict__ vdwFb,
    const float* __restrict__ vdwGW, const float* __restrict__ vdwGb)
{
    int bid = blockIdx.x;
    int tid = threadIdx.x;
    if (bid == 0 && tid == 0) g_order = (p2u[0] > 1000000u) ? 1 : 0;

    if (bid < 126) {
        int layer = bid / 42, rem = bid % 42;
        int half = rem / 21, k = rem % 21;
        const float* fW = (half ? vdwFW : cheFW) + layer * 2560;
        const float* fb = (half ? vdwFb : cheFb) + layer * 128;
        const float* gW = (half ? vdwGW : cheGW) + (size_t)layer * 98304;
        const float* gb = (half ? vdwGb : cheGb) + layer * 256;
        float* We = g_We + (layer * 2 + half) * 5120;
        float* be = g_be + (layer * 2 + half) * 256;
        int c = tid;
        if (k < ERBF) {
            float s = 0.f;
            for (int hh = 0; hh < 128; hh++) s = fmaf(fW[k * 128 + hh], gW[(size_t)(128 + hh) * 256 + c], s);
            We[k * 256 + c] = s;
        } else {
            float s = gb[c];
            for (int hh = 0; hh < 128; hh++) s = fmaf(fb[hh], gW[(size_t)(128 + hh) * 256 + c], s);
            be[c] = s;
        }
    } else {
        int idx = (bid - 126) * 256 + tid;             // [0, 393216)
        int layer = idx >> 17;
        int within = idx & 131071;
        int k = within >> 10;
        int c = within & 1023;
        int region = c >> 8;                           // 0 S_che, 1 T_che, 2 S_vdw, 3 T_vdw
        int cc = c & 255;
        int h = cc >> 1, p = cc & 1;                   // p=0 filt, p=1 core
        const float* gW = ((region < 2) ? cheGW : vdwGW) + (size_t)layer * 98304;
        int row = ((region & 1) ? 256 : 0) + k;
        g_Wcat[idx] = gW[(size_t)row * 256 + p * 128 + h];
    }
}

// ---------------- 2: edge lookup tables via Chebyshev recurrence ----------------
__global__ __launch_bounds__(256) void table_kernel()
{
    int j = blockIdx.x;
    int lh = blockIdx.y;
    int half = lh & 1;
    int cc = threadIdx.x;
    int h = cc >> 1, p = cc & 1;
    int col = p * 128 + h;

    const float* We = g_We + lh * 5120;
    const float* be = g_be + lh * 256;
    float cut  = half ? 12.f : 8.f;
    float dmax = half ? DMAX_VDW : DMAX_CHE;
    float d = (float)j * (dmax / (float)(KNOT - 3));

    float val = be[col];
    if (d < cut) {
        float x = d * (PI_F / cut);
        float s1 = sinf(x), c1 = cosf(x);
        float env = 0.5f * (c1 + 1.f);
        float invd = (d > 1e-6f) ? __fdividef(1.f, d) : 0.f;
        float coef = env * invd;
        float c2 = 2.f * c1;
        float sk = s1, skm = 0.f;
#pragma unroll
        for (int k = 0; k < ERBF; k++) {
            val = fmaf(sk * coef, We[k * 256 + col], val);
            float sn = fmaf(c2, sk, -skm);
            skm = sk; sk = sn;
        }
    }
    g_tab[((size_t)lh * KNOT + j) * 256 + cc] = val;
}

// ---------------- 3: pack table to paired fp16 rows ----------------
__global__ __launch_bounds__(128) void pack_kernel()
{
    int j = blockIdx.x, lh = blockIdx.y, h = threadIdx.x;
    int j1 = (j + 1 < KNOT) ? (j + 1) : (KNOT - 1);
    const float* r0 = g_tab + ((size_t)lh * KNOT + j) * 256;
    const float* r1 = g_tab + ((size_t)lh * KNOT + j1) * 256;
    __half2 a = __floats2half2_rn(r0[2 * h], r0[2 * h + 1]);
    __half2 b = __floats2half2_rn(r1[2 * h], r1[2 * h + 1]);
    uint2 v;
    v.x = *(unsigned*)&a;
    v.y = *(unsigned*)&b;
    g_tab16[((size_t)lh * KNOT + j) * 128 + h] = v;
}

// ---------------- 4: node embedding ----------------
__global__ __launch_bounds__(128) void embed_kernel(
    const float* __restrict__ ae, const float* __restrict__ W, const float* __restrict__ b)
{
    __shared__ float sW[13 * 128];
    __shared__ float sa[16 * 13];
    int h = threadIdx.x;
    for (int i = h; i < 13 * 128; i += 128) sW[i] = W[i];
    int n0 = blockIdx.x * 16;
    for (int i = h; i < 16 * 13; i += 128) sa[i] = ae[n0 * 13 + i];
    float bb = b[h];
    __syncthreads();
#pragma unroll
    for (int nn = 0; nn < 16; nn++) {
        float s = bb;
#pragma unroll
        for (int k = 0; k < 13; k++) s = fmaf(sa[nn * 13 + k], sW[k * 128 + h], s);
        g_nodesA[(size_t)(n0 + nn) * 128 + h] = s;
    }
}

// ---------------- 5: ST GEMM  [N,128]x[128,1024], f32x2, double-buffered, vector LDS ----------------
__global__ __launch_bounds__(256, 2) void gemm_kernel(int src, int layer)
{
    const float* __restrict__ A = src ? g_nodesB : g_nodesA;
    const float* __restrict__ Bm = g_Wcat + (size_t)layer * 131072;
    float* __restrict__ C = g_ST;

    __shared__ __align__(16) float As[2][8][128];
    __shared__ __align__(16) float Bs[2][8][128];

    int r0 = blockIdx.x * 128;
    int c0 = blockIdx.y * 128;
    int tid = threadIdx.x;
    int tx = tid & 15, ty = tid >> 4;

    u64 acc[8][4];
#pragma unroll
    for (int i = 0; i < 8; i++)
#pragma unroll
        for (int j = 0; j < 4; j++) acc[i][j] = pk2(0.f, 0.f);

    int arow = tid >> 1;
    int acol = (tid & 1) * 4;
    int brow = tid >> 5;
    int bcol = (tid & 31) * 4;
    int gr = r0 + arow;
    const float* Aptr = A + (size_t)gr * 128 + acol;
    const float* Bptr = Bm + (size_t)brow * 1024 + c0 + bcol;

    float4 av = make_float4(0.f, 0.f, 0.f, 0.f);
    if (gr < NPTS) av = *(const float4*)Aptr;
    float4 bv = *(const float4*)Bptr;
    As[0][acol + 0][arow] = av.x;
    As[0][acol + 1][arow] = av.y;
    As[0][acol + 2][arow] = av.z;
    As[0][acol + 3][arow] = av.w;
    *(float4*)&Bs[0][brow][bcol] = bv;
    __syncthreads();

#pragma unroll 1
    for (int t = 0; t < 16; t++) {
        int cur = t & 1;
        float4 avn = make_float4(0.f, 0.f, 0.f, 0.f), bvn;
        if (t < 15) {
            if (gr < NPTS) avn = *(const float4*)(Aptr + 8 * (t + 1));
            bvn = *(const float4*)(Bptr + (size_t)8 * (t + 1) * 1024);
        }
#pragma unroll
        for (int k = 0; k < 8; k++) {
            ulonglong2 bb0 = *(const ulonglong2*)&Bs[cur][k][tx * 8];
            ulonglong2 bb1 = *(const ulonglong2*)&Bs[cur][k][tx * 8 + 4];
            float4 a0 = *(const float4*)&As[cur][k][ty * 8];
            float4 a1 = *(const float4*)&As[cur][k][ty * 8 + 4];
            float ar[8] = {a0.x, a0.y, a0.z, a0.w, a1.x, a1.y, a1.z, a1.w};
#pragma unroll
            for (int i = 0; i < 8; i++) {
                u64 a2 = pk2(ar[i], ar[i]);
                acc[i][0] = fma2(a2, bb0.x, acc[i][0]);
                acc[i][1] = fma2(a2, bb0.y, acc[i][1]);
                acc[i][2] = fma2(a2, bb1.x, acc[i][2]);
                acc[i][3] = fma2(a2, bb1.y, acc[i][3]);
            }
        }
        if (t < 15) {
            As[cur ^ 1][acol + 0][arow] = avn.x;
            As[cur ^ 1][acol + 1][arow] = avn.y;
            As[cur ^ 1][acol + 2][arow] = avn.z;
            As[cur ^ 1][acol + 3][arow] = avn.w;
            *(float4*)&Bs[cur ^ 1][brow][bcol] = bvn;
        }
        __syncthreads();
    }

#pragma unroll
    for (int i = 0; i < 8; i++) {
        int gr2 = r0 + ty * 8 + i;
        if (gr2 < NPTS) {
            float4 lo, hi;
            upk2(acc[i][0], lo.x, lo.y);
            upk2(acc[i][1], lo.z, lo.w);
            upk2(acc[i][2], hi.x, hi.y);
            upk2(acc[i][3], hi.z, hi.w);
            *(float4*)(C + (size_t)gr2 * 1024 + c0 + tx * 8) = lo;
            *(float4*)(C + (size_t)gr2 * 1024 + c0 + tx * 8 + 4) = hi;
        }
    }
}

// ---------------- 6: fused gated conv, fp16-paired table rows, 2-deep prefetch ----------------
__global__ __launch_bounds__(128) void conv_kernel(
    const float* __restrict__ che_fea, const float* __restrict__ p2f, const float* __restrict__ p3f,
    const int* __restrict__ p2i, const int* __restrict__ p3i,
    const int* __restrict__ vdw_idx, int src, int layer)
{
    const int* che_idx = g_order ? p3i : p2i;
    const float* vdw_fea = g_order ? p2f : p3f;
    const float* __restrict__ nodes = src ? g_nodesB : g_nodesA;
    float* __restrict__ nodes_out = src ? g_nodesA : g_nodesB;

    __shared__ int  s_idx[NBLK * MNBR];
    __shared__ int  s_j[NBLK * MNBR];
    __shared__ u64  s_fr[NBLK * MNBR];
    __shared__ u64  s_frm[NBLK * MNBR];

    int h = threadIdx.x;
    int h2 = 2 * h;
    int n0 = blockIdx.x * NBLK;

    float accv[NBLK];
#pragma unroll
    for (int i = 0; i < NBLK; i++) accv[i] = 0.f;

#pragma unroll 1
    for (int half = 0; half < 2; half++) {
        const uint2* tabp = g_tab16 + (size_t)(layer * 2 + half) * KNOT * 128 + h;
        const float* feap = half ? vdw_fea : che_fea;
        const int* idxp = half ? vdw_idx : che_idx;
        float scale = half ? ((float)(KNOT - 3) / DMAX_VDW) : ((float)(KNOT - 3) / DMAX_CHE);
        int toff = half ? 768 : 256;
        int soff = half ? 512 : 0;

        __syncthreads();
        for (int i = h; i < NBLK * MNBR; i += 128) {
            float d = feap[n0 * MNBR + i];
            float u = fminf(d * scale, (float)(KNOT - 3));
            float jf = floorf(u);
            float fr = u - jf;
            s_j[i]   = (int)jf * 128;
            s_fr[i]  = pk2(fr, fr);
            s_frm[i] = pk2(1.f - fr, 1.f - fr);
            s_idx[i] = idxp[n0 * MNBR + i];
        }
        __syncthreads();

#pragma unroll 1
        for (int nn = 0; nn < NBLK; nn++) {
            int n = n0 + nn;
            u64 sv = *(const u64*)(g_ST + (size_t)n * 1024 + soff + h2);
            int i0 = nn * MNBR;

            // 2-deep pipeline: gather row + packed table word
            u64  tg0 = *(const u64*)(g_ST + (size_t)s_idx[i0] * 1024 + toff + h2);
            uint2 tp0 = tabp[s_j[i0]];
            u64  tg1 = *(const u64*)(g_ST + (size_t)s_idx[i0 + 1] * 1024 + toff + h2);
            uint2 tp1 = tabp[s_j[i0 + 1]];

            float a = 0.f;
#pragma unroll 1
            for (int m = 0; m < MNBR; m++) {
                u64 tgc = tg0; uint2 tpc = tp0;
                tg0 = tg1; tp0 = tp1;
                int mp = (m + 2 < MNBR) ? (m + 2) : (MNBR - 1);
                tg1 = *(const u64*)(g_ST + (size_t)s_idx[i0 + mp] * 1024 + toff + h2);
                tp1 = tabp[s_j[i0 + mp]];

                float2 t0 = __half22float2(*(__half2*)&tpc.x);
                float2 t1 = __half22float2(*(__half2*)&tpc.y);
                u64 e = fma2(s_fr[i0 + m], pk2(t1.x, t1.y), mul2(s_frm[i0 + m], pk2(t0.x, t0.y)));
                u64 g = add2(add2(sv, tgc), e);
                float gf, gc; upk2(g, gf, gc);
                a += gatef_(gf, gc);
            }
            accv[nn] += a;
        }
    }
#pragma unroll
    for (int nn = 0; nn < NBLK; nn++) {
        int n = n0 + nn;
        float r = nodes[(size_t)n * 128 + h] + accv[nn];
        nodes_out[(size_t)n * 128 + h] = softplusf_(r);
    }
}

// ---------------- 7: pooling + MLP head ----------------
__global__ __launch_bounds__(128) void pool_kernel(
    const int* __restrict__ num_atoms,
    const float* __restrict__ fc1W, const float* __restrict__ fc1b,
    const float* __restrict__ outW, const float* __restrict__ outb,
    float* __restrict__ out, int src)
{
    const float* __restrict__ nodes = src ? g_nodesB : g_nodesA;
    __shared__ float sA[128];
    __shared__ float sB[128];
    __shared__ int sred[128];
    int b = blockIdx.x, h = threadIdx.x;

    int v = 0;
    for (int i = h; i < b; i += 128) v += num_atoms[i];
    sred[h] = v;
    __syncthreads();
    for (int off = 64; off > 0; off >>= 1) {
        if (h < off) sred[h] += sred[h + off];
        __syncthreads();
    }
    int start = sred[0];
    int cnt = num_atoms[b];

    float s = 0.f;
    for (int a = 0; a < cnt; a++) s += nodes[(size_t)(start + a) * 128 + h];
    sA[h] = softplusf_(s / (float)cnt);
    __syncthreads();
    float t = fc1b[h];
    for (int k = 0; k < 128; k++) t = fmaf(sA[k], fc1W[k * 128 + h], t);
    sB[h] = softplusf_(t) * outW[h];
    __syncthreads();
    for (int off = 64; off > 0; off >>= 1) {
        if (h < off) sB[h] += sB[h + off];
        __syncthreads();
    }
    if (h == 0) out[b] = sB[0] + outb[0];
}

// ---------------- launch ----------------
extern "C" void kernel_launch(void* const* d_in, const int* in_sizes, int n_in,
                              void* d_out, int out_size)
{
    const float* ae      = (const float*)d_in[0];
    const float* che_fea = (const float*)d_in[1];
    const void*  p2      = d_in[2];
    const void*  p3      = d_in[3];
    const int*   vdw_idx = (const int*)d_in[4];
    const int*   natoms  = (const int*)d_in[5];
    const float* embW    = (const float*)d_in[6];
    const float* embB    = (const float*)d_in[7];
    const float* cheFW   = (const float*)d_in[8];
    const float* cheFb   = (const float*)d_in[9];
    const float* cheGW   = (const float*)d_in[10];
    const float* cheGb   = (const float*)d_in[11];
    const float* vdwFW   = (const float*)d_in[12];
    const float* vdwFb   = (const float*)d_in[13];
    const float* vdwGW   = (const float*)d_in[14];
    const float* vdwGb   = (const float*)d_in[15];
    const float* fc1W    = (const float*)d_in[16];
    const float* fc1b    = (const float*)d_in[17];
    const float* outW    = (const float*)d_in[18];
    const float* outb    = (const float*)d_in[19];

    prep_kernel<<<126 + 1536, 256>>>((const unsigned*)p2, cheFW, cheFb, cheGW, cheGb,
                                     vdwFW, vdwFb, vdwGW, vdwGb);
    table_kernel<<<dim3(KNOT, 6), 256>>>();
    pack_kernel<<<dim3(KNOT, 6), 128>>>();
    embed_kernel<<<NPTS / 16, 128>>>(ae, embW, embB);

    int src = 0;
    for (int i = 0; i < 3; i++) {
        gemm_kernel<<<dim3((NPTS + 127) / 128, 8), 256>>>(src, i);
        conv_kernel<<<NPTS / NBLK, 128>>>(che_fea, (const float*)p2, (const float*)p3,
                                          (const int*)p2, (const int*)p3, vdw_idx, src, i);
        src ^= 1;
    }
    pool_kernel<<<BCRY, 128>>>(natoms, fc1W, fc1b, outW, outb, (float*)d_out, src);
}

// round 7
// speedup vs baseline: 1.0147x; 1.0147x over previous
#include <cuda_runtime.h>
#include <cuda_fp16.h>
#include <cstdint>

// ---------------- problem constants ----------------
#define NPTS 20000
#define MNBR 20
#define ERBF 20
#define HDIM 128
#define BCRY 200
#define NBLK 8
#define PI_F 3.14159265358979f
#define KNOT 4096
#define DMAX_CHE 8.81f
#define DMAX_VDW 13.21f

typedef unsigned long long u64;

// ---------------- device scratch ----------------
__device__ int   g_order;
__device__ float g_nodesA[NPTS * HDIM];
__device__ float g_nodesB[NPTS * HDIM];
__device__ __half2 g_STh[(size_t)NPTS * 512];            // [S_che|T_che|S_vdw|T_vdw] x 128 half2 (filt,core)
__device__ float g_Wcat[3 * 131072];
__device__ float g_We[3 * 2 * ERBF * 256];
__device__ float g_be[3 * 2 * 256];
__device__ float g_tab[(size_t)3 * 2 * KNOT * 256];      // fp32 scalar table (build stage)
__device__ uint2 g_tab16[(size_t)3 * 2 * KNOT * 128];    // packed fp16: {f_j,c_j,f_j+1,c_j+1} per (j,h)

// ---------------- f32x2 packed math ----------------
__device__ __forceinline__ u64 pk2(float lo, float hi) {
    u64 r; asm("mov.b64 %0, {%1,%2};" : "=l"(r) : "f"(lo), "f"(hi)); return r;
}
__device__ __forceinline__ void upk2(u64 v, float& lo, float& hi) {
    asm("mov.b64 {%0,%1}, %2;" : "=f"(lo), "=f"(hi) : "l"(v));
}
__device__ __forceinline__ u64 fma2(u64 a, u64 b, u64 c) {
    u64 d; asm("fma.rn.f32x2 %0, %1, %2, %3;" : "=l"(d) : "l"(a), "l"(b), "l"(c)); return d;
}
__device__ __forceinline__ u64 add2(u64 a, u64 b) {
    u64 d; asm("add.rn.f32x2 %0, %1, %2;" : "=l"(d) : "l"(a), "l"(b)); return d;
}
__device__ __forceinline__ u64 mul2(u64 a, u64 b) {
    u64 d; asm("mul.rn.f32x2 %0, %1, %2;" : "=l"(d) : "l"(a), "l"(b)); return d;
}

// ---------------- activations ----------------
__device__ __forceinline__ float softplusf_(float x) {
    return fmaxf(x, 0.f) + __logf(1.f + __expf(-fabsf(x)));
}
__device__ __forceinline__ float gatef_(float f, float c) {
    float sig = __fdividef(1.f, 1.f + __expf(-f));
    return sig * softplusf_(c);
}

// ---------------- 1: merged prep: detect + folded edge weights + Wcat ----------------
__global__ __launch_bounds__(256) void prep_kernel(
    const unsigned* __restrict__ p2u,
    const float* __restrict__ cheFW, const float* __restrict__ cheFb,
    const float* __restrict__ cheGW, const float* __restrict__ cheGb,
    const float* __restrict__ vdwFW, const float* __restrict__ vdwFb,
    const float* __restrict__ vdwGW, const float* __restrict__ vdwGb)
{
    int bid = blockIdx.x;
    int tid = threadIdx.x;
    if (bid == 0 && tid == 0) g_order = (p2u[0] > 1000000u) ? 1 : 0;

    if (bid < 126) {
        int layer = bid / 42, rem = bid % 42;
        int half = rem / 21, k = rem % 21;
        const float* fW = (half ? vdwFW : cheFW) + layer * 2560;
        const float* fb = (half ? vdwFb : cheFb) + layer * 128;
        const float* gW = (half ? vdwGW : cheGW) + (size_t)layer * 98304;
        const float* gb = (half ? vdwGb : cheGb) + layer * 256;
        float* We = g_We + (layer * 2 + half) * 5120;
        float* be = g_be + (layer * 2 + half) * 256;
        int c = tid;
        if (k < ERBF) {
            float s = 0.f;
            for (int hh = 0; hh < 128; hh++) s = fmaf(fW[k * 128 + hh], gW[(size_t)(128 + hh) * 256 + c], s);
            We[k * 256 + c] = s;
        } else {
            float s = gb[c];
            for (int hh = 0; hh < 128; hh++) s = fmaf(fb[hh], gW[(size_t)(128 + hh) * 256 + c], s);
            be[c] = s;
        }
    } else {
        int idx = (bid - 126) * 256 + tid;             // [0, 393216)
        int layer = idx >> 17;
        int within = idx & 131071;
        int k = within >> 10;
        int c = within & 1023;
        int region = c >> 8;                           // 0 S_che, 1 T_che, 2 S_vdw, 3 T_vdw
        int cc = c & 255;
        int h = cc >> 1, p = cc & 1;                   // p=0 filt, p=1 core
        const float* gW = ((region < 2) ? cheGW : vdwGW) + (size_t)layer * 98304;
        int row = ((region & 1) ? 256 : 0) + k;
        g_Wcat[idx] = gW[(size_t)row * 256 + p * 128 + h];
    }
}

// ---------------- 2: edge lookup tables via Chebyshev recurrence ----------------
__global__ __launch_bounds__(256) void table_kernel()
{
    int j = blockIdx.x;
    int lh = blockIdx.y;
    int half = lh & 1;
    int cc = threadIdx.x;
    int h = cc >> 1, p = cc & 1;
    int col = p * 128 + h;

    const float* We = g_We + lh * 5120;
    const float* be = g_be + lh * 256;
    float cut  = half ? 12.f : 8.f;
    float dmax = half ? DMAX_VDW : DMAX_CHE;
    float d = (float)j * (dmax / (float)(KNOT - 3));

    float val = be[col];
    if (d < cut) {
        float x = d * (PI_F / cut);
        float s1 = sinf(x), c1 = cosf(x);
        float env = 0.5f * (c1 + 1.f);
        float invd = (d > 1e-6f) ? __fdividef(1.f, d) : 0.f;
        float coef = env * invd;
        float c2 = 2.f * c1;
        float sk = s1, skm = 0.f;
#pragma unroll
        for (int k = 0; k < ERBF; k++) {
            val = fmaf(sk * coef, We[k * 256 + col], val);
            float sn = fmaf(c2, sk, -skm);
            skm = sk; sk = sn;
        }
    }
    g_tab[((size_t)lh * KNOT + j) * 256 + cc] = val;
}

// ---------------- 3: pack table to paired fp16 rows ----------------
__global__ __launch_bounds__(128) void pack_kernel()
{
    int j = blockIdx.x, lh = blockIdx.y, h = threadIdx.x;
    int j1 = (j + 1 < KNOT) ? (j + 1) : (KNOT - 1);
    const float* r0 = g_tab + ((size_t)lh * KNOT + j) * 256;
    const float* r1 = g_tab + ((size_t)lh * KNOT + j1) * 256;
    __half2 a = __floats2half2_rn(r0[2 * h], r0[2 * h + 1]);
    __half2 b = __floats2half2_rn(r1[2 * h], r1[2 * h + 1]);
    uint2 v;
    v.x = *(unsigned*)&a;
    v.y = *(unsigned*)&b;
    g_tab16[((size_t)lh * KNOT + j) * 128 + h] = v;
}

// ---------------- 4: node embedding ----------------
__global__ __launch_bounds__(128) void embed_kernel(
    const float* __restrict__ ae, const float* __restrict__ W, const float* __restrict__ b)
{
    __shared__ float sW[13 * 128];
    __shared__ float sa[16 * 13];
    int h = threadIdx.x;
    for (int i = h; i < 13 * 128; i += 128) sW[i] = W[i];
    int n0 = blockIdx.x * 16;
    for (int i = h; i < 16 * 13; i += 128) sa[i] = ae[n0 * 13 + i];
    float bb = b[h];
    __syncthreads();
#pragma unroll
    for (int nn = 0; nn < 16; nn++) {
        float s = bb;
#pragma unroll
        for (int k = 0; k < 13; k++) s = fmaf(sa[nn * 13 + k], sW[k * 128 + h], s);
        g_nodesA[(size_t)(n0 + nn) * 128 + h] = s;
    }
}

// ---------------- 5: ST GEMM  [N,128]x[128,1024], f32x2, double-buffered (r4 mainloop), fp16 epilogue ----------------
__global__ __launch_bounds__(256, 2) void gemm_kernel(int src, int layer)
{
    const float* __restrict__ A = src ? g_nodesB : g_nodesA;
    const float* __restrict__ Bm = g_Wcat + (size_t)layer * 131072;

    __shared__ __align__(16) float As[2][8][128];
    __shared__ __align__(16) float Bs[2][8][128];

    int r0 = blockIdx.x * 128;
    int c0 = blockIdx.y * 128;
    int tid = threadIdx.x;
    int tx = tid & 15, ty = tid >> 4;

    u64 acc[8][4];
#pragma unroll
    for (int i = 0; i < 8; i++)
#pragma unroll
        for (int j = 0; j < 4; j++) acc[i][j] = pk2(0.f, 0.f);

    int arow = tid >> 1;
    int acol = (tid & 1) * 4;
    int brow = tid >> 5;
    int bcol = (tid & 31) * 4;
    int gr = r0 + arow;
    const float* Aptr = A + (size_t)gr * 128 + acol;
    const float* Bptr = Bm + (size_t)brow * 1024 + c0 + bcol;

    float4 av = make_float4(0.f, 0.f, 0.f, 0.f);
    if (gr < NPTS) av = *(const float4*)Aptr;
    float4 bv = *(const float4*)Bptr;
    As[0][acol + 0][arow] = av.x;
    As[0][acol + 1][arow] = av.y;
    As[0][acol + 2][arow] = av.z;
    As[0][acol + 3][arow] = av.w;
    *(float4*)&Bs[0][brow][bcol] = bv;
    __syncthreads();

#pragma unroll 1
    for (int t = 0; t < 16; t++) {
        int cur = t & 1;
        float4 avn = make_float4(0.f, 0.f, 0.f, 0.f), bvn;
        if (t < 15) {
            if (gr < NPTS) avn = *(const float4*)(Aptr + 8 * (t + 1));
            bvn = *(const float4*)(Bptr + (size_t)8 * (t + 1) * 1024);
        }
#pragma unroll
        for (int k = 0; k < 8; k++) {
            ulonglong2 bb0 = *(const ulonglong2*)&Bs[cur][k][tx * 8];
            ulonglong2 bb1 = *(const ulonglong2*)&Bs[cur][k][tx * 8 + 4];
#pragma unroll
            for (int i = 0; i < 8; i++) {
                float a_ = As[cur][k][ty * 8 + i];
                u64 a2 = pk2(a_, a_);
                acc[i][0] = fma2(a2, bb0.x, acc[i][0]);
                acc[i][1] = fma2(a2, bb0.y, acc[i][1]);
                acc[i][2] = fma2(a2, bb1.x, acc[i][2]);
                acc[i][3] = fma2(a2, bb1.y, acc[i][3]);
            }
        }
        if (t < 15) {
            As[cur ^ 1][acol + 0][arow] = avn.x;
            As[cur ^ 1][acol + 1][arow] = avn.y;
            As[cur ^ 1][acol + 2][arow] = avn.z;
            As[cur ^ 1][acol + 3][arow] = avn.w;
            *(float4*)&Bs[cur ^ 1][brow][bcol] = bvn;
        }
        __syncthreads();
    }

    // fp16 epilogue: 8 floats -> 4 half2 -> one uint4 store
#pragma unroll
    for (int i = 0; i < 8; i++) {
        int gr2 = r0 + ty * 8 + i;
        if (gr2 < NPTS) {
            float x0, x1, x2, x3, x4, x5, x6, x7;
            upk2(acc[i][0], x0, x1);
            upk2(acc[i][1], x2, x3);
            upk2(acc[i][2], x4, x5);
            upk2(acc[i][3], x6, x7);
            __half2 h0 = __floats2half2_rn(x0, x1);
            __half2 h1 = __floats2half2_rn(x2, x3);
            __half2 h2 = __floats2half2_rn(x4, x5);
            __half2 h3 = __floats2half2_rn(x6, x7);
            uint4 v;
            v.x = *(unsigned*)&h0; v.y = *(unsigned*)&h1;
            v.z = *(unsigned*)&h2; v.w = *(unsigned*)&h3;
            *(uint4*)(g_STh + (size_t)gr2 * 512 + (c0 >> 1) + tx * 4) = v;
        }
    }
}

// ---------------- 6: fused gated conv, fp16 ST + fp16-paired table, 2-deep prefetch ----------------
__global__ __launch_bounds__(128) void conv_kernel(
    const float* __restrict__ che_fea, const float* __restrict__ p2f, const float* __restrict__ p3f,
    const int* __restrict__ p2i, const int* __restrict__ p3i,
    const int* __restrict__ vdw_idx, int src, int layer)
{
    const int* che_idx = g_order ? p3i : p2i;
    const float* vdw_fea = g_order ? p2f : p3f;
    const float* __restrict__ nodes = src ? g_nodesB : g_nodesA;
    float* __restrict__ nodes_out = src ? g_nodesA : g_nodesB;

    __shared__ int  s_idx[NBLK * MNBR];
    __shared__ int  s_j[NBLK * MNBR];
    __shared__ u64  s_fr[NBLK * MNBR];
    __shared__ u64  s_frm[NBLK * MNBR];

    int h = threadIdx.x;
    int n0 = blockIdx.x * NBLK;

    float accv[NBLK];
#pragma unroll
    for (int i = 0; i < NBLK; i++) accv[i] = 0.f;

#pragma unroll 1
    for (int half = 0; half < 2; half++) {
        const uint2* tabp = g_tab16 + (size_t)(layer * 2 + half) * KNOT * 128 + h;
        const float* feap = half ? vdw_fea : che_fea;
        const int* idxp = half ? vdw_idx : che_idx;
        float scale = half ? ((float)(KNOT - 3) / DMAX_VDW) : ((float)(KNOT - 3) / DMAX_CHE);
        int toff = (half ? 384 : 128) + h;   // T region, half2 units
        int soff = (half ? 256 : 0) + h;     // S region

        __syncthreads();
        for (int i = h; i < NBLK * MNBR; i += 128) {
            float d = feap[n0 * MNBR + i];
            float u = fminf(d * scale, (float)(KNOT - 3));
            float jf = floorf(u);
            float fr = u - jf;
            s_j[i]   = (int)jf * 128;
            s_fr[i]  = pk2(fr, fr);
            s_frm[i] = pk2(1.f - fr, 1.f - fr);
            s_idx[i] = idxp[n0 * MNBR + i];
        }
        __syncthreads();

#pragma unroll 1
        for (int nn = 0; nn < NBLK; nn++) {
            int n = n0 + nn;
            float2 svf = __half22float2(g_STh[(size_t)n * 512 + soff]);
            u64 sv = pk2(svf.x, svf.y);
            int i0 = nn * MNBR;

            // 2-deep pipeline: half2 gather + packed table word
            __half2 tg0 = g_STh[(size_t)s_idx[i0] * 512 + toff];
            uint2   tp0 = tabp[s_j[i0]];
            __half2 tg1 = g_STh[(size_t)s_idx[i0 + 1] * 512 + toff];
            uint2   tp1 = tabp[s_j[i0 + 1]];

            float a = 0.f;
#pragma unroll 1
            for (int m = 0; m < MNBR; m++) {
                __half2 tgc = tg0; uint2 tpc = tp0;
                tg0 = tg1; tp0 = tp1;
                int mp = (m + 2 < MNBR) ? (m + 2) : (MNBR - 1);
                tg1 = g_STh[(size_t)s_idx[i0 + mp] * 512 + toff];
                tp1 = tabp[s_j[i0 + mp]];

                float2 tgf = __half22float2(tgc);
                float2 t0 = __half22float2(*(__half2*)&tpc.x);
                float2 t1 = __half22float2(*(__half2*)&tpc.y);
                u64 e = fma2(s_fr[i0 + m], pk2(t1.x, t1.y), mul2(s_frm[i0 + m], pk2(t0.x, t0.y)));
                u64 g = add2(add2(sv, pk2(tgf.x, tgf.y)), e);
                float gf, gc; upk2(g, gf, gc);
                a += gatef_(gf, gc);
            }
            accv[nn] += a;
        }
    }
#pragma unroll
    for (int nn = 0; nn < NBLK; nn++) {
        int n = n0 + nn;
        float r = nodes[(size_t)n * 128 + h] + accv[nn];
        nodes_out[(size_t)n * 128 + h] = softplusf_(r);
    }
}

// ---------------- 7: pooling + MLP head ----------------
__global__ __launch_bounds__(128) void pool_kernel(
    const int* __restrict__ num_atoms,
    const float* __restrict__ fc1W, const float* __restrict__ fc1b,
    const float* __restrict__ outW, const float* __restrict__ outb,
    float* __restrict__ out, int src)
{
    const float* __restrict__ nodes = src ? g_nodesB : g_nodesA;
    __shared__ float sA[128];
    __shared__ float sB[128];
    __shared__ int sred[128];
    int b = blockIdx.x, h = threadIdx.x;

    int v = 0;
    for (int i = h; i < b; i += 128) v += num_atoms[i];
    sred[h] = v;
    __syncthreads();
    for (int off = 64; off > 0; off >>= 1) {
        if (h < off) sred[h] += sred[h + off];
        __syncthreads();
    }
    int start = sred[0];
    int cnt = num_atoms[b];

    float s = 0.f;
    for (int a = 0; a < cnt; a++) s += nodes[(size_t)(start + a) * 128 + h];
    sA[h] = softplusf_(s / (float)cnt);
    __syncthreads();
    float t = fc1b[h];
    for (int k = 0; k < 128; k++) t = fmaf(sA[k], fc1W[k * 128 + h], t);
    sB[h] = softplusf_(t) * outW[h];
    __syncthreads();
    for (int off = 64; off > 0; off >>= 1) {
        if (h < off) sB[h] += sB[h + off];
        __syncthreads();
    }
    if (h == 0) out[b] = sB[0] + outb[0];
}

// ---------------- launch ----------------
extern "C" void kernel_launch(void* const* d_in, const int* in_sizes, int n_in,
                              void* d_out, int out_size)
{
    const float* ae      = (const float*)d_in[0];
    const float* che_fea = (const float*)d_in[1];
    const void*  p2      = d_in[2];
    const void*  p3      = d_in[3];
    const int*   vdw_idx = (const int*)d_in[4];
    const int*   natoms  = (const int*)d_in[5];
    const float* embW    = (const float*)d_in[6];
    const float* embB    = (const float*)d_in[7];
    const float* cheFW   = (const float*)d_in[8];
    const float* cheFb   = (const float*)d_in[9];
    const float* cheGW   = (const float*)d_in[10];
    const float* cheGb   = (const float*)d_in[11];
    const float* vdwFW   = (const float*)d_in[12];
    const float* vdwFb   = (const float*)d_in[13];
    const float* vdwGW   = (const float*)d_in[14];
    const float* vdwGb   = (const float*)d_in[15];
    const float* fc1W    = (const float*)d_in[16];
    const float* fc1b    = (const float*)d_in[17];
    const float* outW    = (const float*)d_in[18];
    const float* outb    = (const float*)d_in[19];

    prep_kernel<<<126 + 1536, 256>>>((const unsigned*)p2, cheFW, cheFb, cheGW, cheGb,
                                     vdwFW, vdwFb, vdwGW, vdwGb);
    table_kernel<<<dim3(KNOT, 6), 256>>>();
    pack_kernel<<<dim3(KNOT, 6), 128>>>();
    embed_kernel<<<NPTS / 16, 128>>>(ae, embW, embB);

    int src = 0;
    for (int i = 0; i < 3; i++) {
        gemm_kernel<<<dim3((NPTS + 127) / 128, 8), 256>>>(src, i);
        conv_kernel<<<NPTS / NBLK, 128>>>(che_fea, (const float*)p2, (const float*)p3,
                                          (const int*)p2, (const int*)p3, vdw_idx, src, i);
        src ^= 1;
    }
    pool_kernel<<<BCRY, 128>>>(natoms, fc1W, fc1b, outW, outb, (float*)d_out, src);
}

// round 8
// speedup vs baseline: 1.1796x; 1.1626x over previous
#include <cuda_runtime.h>
#include <cuda_fp16.h>
#include <cstdint>

// ---------------- problem constants ----------------
#define NPTS 20000
#define MNBR 20
#define ERBF 20
#define HDIM 128
#define BCRY 200
#define NBLK 8
#define PI_F 3.14159265358979f
#define KNOT 4096
#define DMAX_CHE 8.81f
#define DMAX_VDW 13.21f

typedef unsigned long long u64;

// ---------------- device scratch ----------------
__device__ int   g_order;
__device__ float g_nodesA[NPTS * HDIM];
__device__ float g_nodesB[NPTS * HDIM];
__device__ __half2 g_STh[(size_t)NPTS * 512];            // [S_che|T_che|S_vdw|T_vdw] x 128 half2 (filt,core)
__device__ float g_Wcat[3 * 131072];
__device__ float g_We[3 * 2 * ERBF * 256];
__device__ float g_be[3 * 2 * 256];
__device__ uint2 g_tab16[(size_t)3 * 2 * KNOT * 128];    // packed fp16: {f_j,c_j,f_j+1,c_j+1} per (j,h)

// ---------------- f32x2 packed math ----------------
__device__ __forceinline__ u64 pk2(float lo, float hi) {
    u64 r; asm("mov.b64 %0, {%1,%2};" : "=l"(r) : "f"(lo), "f"(hi)); return r;
}
__device__ __forceinline__ void upk2(u64 v, float& lo, float& hi) {
    asm("mov.b64 {%0,%1}, %2;" : "=f"(lo), "=f"(hi) : "l"(v));
}
__device__ __forceinline__ u64 fma2(u64 a, u64 b, u64 c) {
    u64 d; asm("fma.rn.f32x2 %0, %1, %2, %3;" : "=l"(d) : "l"(a), "l"(b), "l"(c)); return d;
}
__device__ __forceinline__ u64 add2(u64 a, u64 b) {
    u64 d; asm("add.rn.f32x2 %0, %1, %2;" : "=l"(d) : "l"(a), "l"(b)); return d;
}
__device__ __forceinline__ u64 mul2(u64 a, u64 b) {
    u64 d; asm("mul.rn.f32x2 %0, %1, %2;" : "=l"(d) : "l"(a), "l"(b)); return d;
}

// ---------------- activations ----------------
__device__ __forceinline__ float softplusf_(float x) {
    return fmaxf(x, 0.f) + __logf(1.f + __expf(-fabsf(x)));
}
__device__ __forceinline__ float gatef_(float f, float c) {
    float sig = __fdividef(1.f, 1.f + __expf(-f));
    return sig * softplusf_(c);
}

// ---------------- 1: merged prep: detect + folded edge weights + Wcat + embed ----------------
__global__ __launch_bounds__(256) void prep_kernel(
    const unsigned* __restrict__ p2u,
    const float* __restrict__ ae, const float* __restrict__ embW, const float* __restrict__ embB,
    const float* __restrict__ cheFW, const float* __restrict__ cheFb,
    const float* __restrict__ cheGW, const float* __restrict__ cheGb,
    const float* __restrict__ vdwFW, const float* __restrict__ vdwFb,
    const float* __restrict__ vdwGW, const float* __restrict__ vdwGb)
{
    int bid = blockIdx.x;
    int tid = threadIdx.x;
    if (bid == 0 && tid == 0) g_order = (p2u[0] > 1000000u) ? 1 : 0;

    if (bid < 126) {
        // folded edge weights
        int layer = bid / 42, rem = bid % 42;
        int half = rem / 21, k = rem % 21;
        const float* fW = (half ? vdwFW : cheFW) + layer * 2560;
        const float* fb = (half ? vdwFb : cheFb) + layer * 128;
        const float* gW = (half ? vdwGW : cheGW) + (size_t)layer * 98304;
        const float* gb = (half ? vdwGb : cheGb) + layer * 256;
        float* We = g_We + (layer * 2 + half) * 5120;
        float* be = g_be + (layer * 2 + half) * 256;
        int c = tid;
        if (k < ERBF) {
            float s = 0.f;
            for (int hh = 0; hh < 128; hh++) s = fmaf(fW[k * 128 + hh], gW[(size_t)(128 + hh) * 256 + c], s);
            We[k * 256 + c] = s;
        } else {
            float s = gb[c];
            for (int hh = 0; hh < 128; hh++) s = fmaf(fb[hh], gW[(size_t)(128 + hh) * 256 + c], s);
            be[c] = s;
        }
    } else if (bid < 126 + 1536) {
        // Wcat build
        int idx = (bid - 126) * 256 + tid;             // [0, 393216)
        int layer = idx >> 17;
        int within = idx & 131071;
        int k = within >> 10;
        int c = within & 1023;
        int region = c >> 8;                           // 0 S_che, 1 T_che, 2 S_vdw, 3 T_vdw
        int cc = c & 255;
        int h = cc >> 1, p = cc & 1;                   // p=0 filt, p=1 core
        const float* gW = ((region < 2) ? cheGW : vdwGW) + (size_t)layer * 98304;
        int row = ((region & 1) ? 256 : 0) + k;
        g_Wcat[idx] = gW[(size_t)row * 256 + p * 128 + h];
    } else {
        // node embedding: 32 nodes per block, 2 groups of 128 threads
        __shared__ float sW[13 * 128];
        __shared__ float sa[32 * 13];
        int h = tid & 127, grp = tid >> 7;
        int n0 = (bid - (126 + 1536)) * 32;
        for (int i = tid; i < 13 * 128; i += 256) sW[i] = embW[i];
        for (int i = tid; i < 32 * 13; i += 256) sa[i] = ae[n0 * 13 + i];
        float bb = embB[h];
        __syncthreads();
#pragma unroll
        for (int nn = 0; nn < 16; nn++) {
            int ln = grp * 16 + nn;
            float s = bb;
#pragma unroll
            for (int k = 0; k < 13; k++) s = fmaf(sa[ln * 13 + k], sW[k * 128 + h], s);
            g_nodesA[(size_t)(n0 + ln) * 128 + h] = s;
        }
    }
}

// ---------------- 2: edge lookup tables (Chebyshev) -> packed fp16 pairs directly ----------------
__global__ __launch_bounds__(128) void table16_kernel()
{
    int j = blockIdx.x, lh = blockIdx.y, half = lh & 1, h = threadIdx.x;
    const float* We = g_We + lh * 5120;
    float bef = g_be[lh * 256 + h];
    float bec = g_be[lh * 256 + 128 + h];
    float cut  = half ? 12.f : 8.f;
    float dmax = half ? DMAX_VDW : DMAX_CHE;
    float step = dmax / (float)(KNOT - 3);
    int j1 = (j + 1 < KNOT) ? (j + 1) : (KNOT - 1);
    float d0 = (float)j * step, d1 = (float)j1 * step;

    float x0 = d0 * (PI_F / cut), x1 = d1 * (PI_F / cut);
    float sn_0 = sinf(x0), cs_0 = cosf(x0);
    float sn_1 = sinf(x1), cs_1 = cosf(x1);
    float coef0 = (d0 < cut && d0 > 1e-6f) ? 0.5f * (cs_0 + 1.f) / d0 : 0.f;
    float coef1 = (d1 < cut && d1 > 1e-6f) ? 0.5f * (cs_1 + 1.f) / d1 : 0.f;
    float c20 = 2.f * cs_0, c21 = 2.f * cs_1;
    float sk0 = sn_0, skm0 = 0.f, sk1 = sn_1, skm1 = 0.f;
    float f0 = bef, c0 = bec, f1 = bef, c1 = bec;
#pragma unroll
    for (int k = 0; k < ERBF; k++) {
        float wf = We[k * 256 + h], wc = We[k * 256 + 128 + h];
        float r0 = sk0 * coef0, r1 = sk1 * coef1;
        f0 = fmaf(r0, wf, f0); c0 = fmaf(r0, wc, c0);
        f1 = fmaf(r1, wf, f1); c1 = fmaf(r1, wc, c1);
        float t0 = fmaf(c20, sk0, -skm0); skm0 = sk0; sk0 = t0;
        float t1 = fmaf(c21, sk1, -skm1); skm1 = sk1; sk1 = t1;
    }
    __half2 a = __floats2half2_rn(f0, c0);
    __half2 b = __floats2half2_rn(f1, c1);
    uint2 v;
    v.x = *(unsigned*)&a;
    v.y = *(unsigned*)&b;
    g_tab16[((size_t)lh * KNOT + j) * 128 + h] = v;
}

// ---------------- 3: ST GEMM  [N,128]x[128,1024], f32x2, double-buffered, fp16 epilogue ----------------
__global__ __launch_bounds__(256, 2) void gemm_kernel(int src, int layer)
{
    const float* __restrict__ A = src ? g_nodesB : g_nodesA;
    const float* __restrict__ Bm = g_Wcat + (size_t)layer * 131072;

    __shared__ __align__(16) float As[2][8][128];
    __shared__ __align__(16) float Bs[2][8][128];

    int r0 = blockIdx.x * 128;
    int c0 = blockIdx.y * 128;
    int tid = threadIdx.x;
    int tx = tid & 15, ty = tid >> 4;

    u64 acc[8][4];
#pragma unroll
    for (int i = 0; i < 8; i++)
#pragma unroll
        for (int j = 0; j < 4; j++) acc[i][j] = pk2(0.f, 0.f);

    int arow = tid >> 1;
    int acol = (tid & 1) * 4;
    int brow = tid >> 5;
    int bcol = (tid & 31) * 4;
    int gr = r0 + arow;
    const float* Aptr = A + (size_t)gr * 128 + acol;
    const float* Bptr = Bm + (size_t)brow * 1024 + c0 + bcol;

    float4 av = make_float4(0.f, 0.f, 0.f, 0.f);
    if (gr < NPTS) av = *(const float4*)Aptr;
    float4 bv = *(const float4*)Bptr;
    As[0][acol + 0][arow] = av.x;
    As[0][acol + 1][arow] = av.y;
    As[0][acol + 2][arow] = av.z;
    As[0][acol + 3][arow] = av.w;
    *(float4*)&Bs[0][brow][bcol] = bv;
    __syncthreads();

#pragma unroll 1
    for (int t = 0; t < 16; t++) {
        int cur = t & 1;
        float4 avn = make_float4(0.f, 0.f, 0.f, 0.f), bvn;
        if (t < 15) {
            if (gr < NPTS) avn = *(const float4*)(Aptr + 8 * (t + 1));
            bvn = *(const float4*)(Bptr + (size_t)8 * (t + 1) * 1024);
        }
#pragma unroll
        for (int k = 0; k < 8; k++) {
            ulonglong2 bb0 = *(const ulonglong2*)&Bs[cur][k][tx * 8];
            ulonglong2 bb1 = *(const ulonglong2*)&Bs[cur][k][tx * 8 + 4];
#pragma unroll
            for (int i = 0; i < 8; i++) {
                float a_ = As[cur][k][ty * 8 + i];
                u64 a2 = pk2(a_, a_);
                acc[i][0] = fma2(a2, bb0.x, acc[i][0]);
                acc[i][1] = fma2(a2, bb0.y, acc[i][1]);
                acc[i][2] = fma2(a2, bb1.x, acc[i][2]);
                acc[i][3] = fma2(a2, bb1.y, acc[i][3]);
            }
        }
        if (t < 15) {
            As[cur ^ 1][acol + 0][arow] = avn.x;
            As[cur ^ 1][acol + 1][arow] = avn.y;
            As[cur ^ 1][acol + 2][arow] = avn.z;
            As[cur ^ 1][acol + 3][arow] = avn.w;
            *(float4*)&Bs[cur ^ 1][brow][bcol] = bvn;
        }
        __syncthreads();
    }

#pragma unroll
    for (int i = 0; i < 8; i++) {
        int gr2 = r0 + ty * 8 + i;
        if (gr2 < NPTS) {
            float x0, x1, x2, x3, x4, x5, x6, x7;
            upk2(acc[i][0], x0, x1);
            upk2(acc[i][1], x2, x3);
            upk2(acc[i][2], x4, x5);
            upk2(acc[i][3], x6, x7);
            __half2 h0 = __floats2half2_rn(x0, x1);
            __half2 h1 = __floats2half2_rn(x2, x3);
            __half2 h2 = __floats2half2_rn(x4, x5);
            __half2 h3 = __floats2half2_rn(x6, x7);
            uint4 v;
            v.x = *(unsigned*)&h0; v.y = *(unsigned*)&h1;
            v.z = *(unsigned*)&h2; v.w = *(unsigned*)&h3;
            *(uint4*)(g_STh + (size_t)gr2 * 512 + (c0 >> 1) + tx * 4) = v;
        }
    }
}

// ---------------- 4: fused gated conv — 2-node interleaved pipelines ----------------
__global__ __launch_bounds__(128) void conv_kernel(
    const float* __restrict__ che_fea, const float* __restrict__ p2f, const float* __restrict__ p3f,
    const int* __restrict__ p2i, const int* __restrict__ p3i,
    const int* __restrict__ vdw_idx, int src, int layer)
{
    const int* che_idx = g_order ? p3i : p2i;
    const float* vdw_fea = g_order ? p2f : p3f;
    const float* __restrict__ nodes = src ? g_nodesB : g_nodesA;
    float* __restrict__ nodes_out = src ? g_nodesA : g_nodesB;

    __shared__ int  s_idx[NBLK * MNBR];
    __shared__ int  s_j[NBLK * MNBR];
    __shared__ u64  s_fr[NBLK * MNBR];
    __shared__ u64  s_frm[NBLK * MNBR];
    __shared__ float s_acc[NBLK * 128];

    int h = threadIdx.x;
    int n0 = blockIdx.x * NBLK;
#pragma unroll
    for (int i = 0; i < NBLK; i++) s_acc[i * 128 + h] = 0.f;

#pragma unroll 1
    for (int half = 0; half < 2; half++) {
        const uint2* tabp = g_tab16 + (size_t)(layer * 2 + half) * KNOT * 128 + h;
        const float* feap = half ? vdw_fea : che_fea;
        const int* idxp = half ? vdw_idx : che_idx;
        float scale = half ? ((float)(KNOT - 3) / DMAX_VDW) : ((float)(KNOT - 3) / DMAX_CHE);
        int toff = (half ? 384 : 128) + h;   // T region, half2 units
        int soff = (half ? 256 : 0) + h;     // S region

        __syncthreads();
        for (int i = h; i < NBLK * MNBR; i += 128) {
            float d = feap[n0 * MNBR + i];
            float u = fminf(d * scale, (float)(KNOT - 3));
            float jf = floorf(u);
            float fr = u - jf;
            s_j[i]   = (int)jf * 128;
            s_fr[i]  = pk2(fr, fr);
            s_frm[i] = pk2(1.f - fr, 1.f - fr);
            s_idx[i] = idxp[n0 * MNBR + i];
        }
        __syncthreads();

#pragma unroll 1
        for (int nn = 0; nn < NBLK; nn += 2) {
            int nA = n0 + nn, nB = nA + 1;
            int iA = nn * MNBR, iB = iA + MNBR;
            float2 svAf = __half22float2(g_STh[(size_t)nA * 512 + soff]);
            float2 svBf = __half22float2(g_STh[(size_t)nB * 512 + soff]);
            u64 svA = pk2(svAf.x, svAf.y);
            u64 svB = pk2(svBf.x, svBf.y);

            // 2-deep pipelines for two nodes (4 loads in flight each kind)
            __half2 tgA0 = g_STh[(size_t)s_idx[iA]     * 512 + toff];
            __half2 tgA1 = g_STh[(size_t)s_idx[iA + 1] * 512 + toff];
            __half2 tgB0 = g_STh[(size_t)s_idx[iB]     * 512 + toff];
            __half2 tgB1 = g_STh[(size_t)s_idx[iB + 1] * 512 + toff];
            uint2 tpA0 = tabp[s_j[iA]];
            uint2 tpA1 = tabp[s_j[iA + 1]];
            uint2 tpB0 = tabp[s_j[iB]];
            uint2 tpB1 = tabp[s_j[iB + 1]];

            float aA = 0.f, aB = 0.f;
#pragma unroll 1
            for (int m = 0; m < MNBR; m++) {
                int mp = (m + 2 < MNBR) ? (m + 2) : (MNBR - 1);
                __half2 tgAc = tgA0; tgA0 = tgA1;
                tgA1 = g_STh[(size_t)s_idx[iA + mp] * 512 + toff];
                __half2 tgBc = tgB0; tgB0 = tgB1;
                tgB1 = g_STh[(size_t)s_idx[iB + mp] * 512 + toff];
                uint2 tpAc = tpA0; tpA0 = tpA1;
                tpA1 = tabp[s_j[iA + mp]];
                uint2 tpBc = tpB0; tpB0 = tpB1;
                tpB1 = tabp[s_j[iB + mp]];

                {
                    float2 tf = __half22float2(tgAc);
                    float2 t0 = __half22float2(*(__half2*)&tpAc.x);
                    float2 t1 = __half22float2(*(__half2*)&tpAc.y);
                    u64 e = fma2(s_fr[iA + m], pk2(t1.x, t1.y), mul2(s_frm[iA + m], pk2(t0.x, t0.y)));
                    u64 g = add2(add2(svA, pk2(tf.x, tf.y)), e);
                    float gf, gc; upk2(g, gf, gc);
                    aA += gatef_(gf, gc);
                }
                {
                    float2 tf = __half22float2(tgBc);
                    float2 t0 = __half22float2(*(__half2*)&tpBc.x);
                    float2 t1 = __half22float2(*(__half2*)&tpBc.y);
                    u64 e = fma2(s_fr[iB + m], pk2(t1.x, t1.y), mul2(s_frm[iB + m], pk2(t0.x, t0.y)));
                    u64 g = add2(add2(svB, pk2(tf.x, tf.y)), e);
                    float gf, gc; upk2(g, gf, gc);
                    aB += gatef_(gf, gc);
                }
            }
            s_acc[nn * 128 + h]       += aA;
            s_acc[(nn + 1) * 128 + h] += aB;
        }
    }
#pragma unroll
    for (int nn = 0; nn < NBLK; nn++) {
        int n = n0 + nn;
        float r = nodes[(size_t)n * 128 + h] + s_acc[nn * 128 + h];
        nodes_out[(size_t)n * 128 + h] = softplusf_(r);
    }
}

// ---------------- 5: pooling + MLP head ----------------
__global__ __launch_bounds__(128) void pool_kernel(
    const int* __restrict__ num_atoms,
    const float* __restrict__ fc1W, const float* __restrict__ fc1b,
    const float* __restrict__ outW, const float* __restrict__ outb,
    float* __restrict__ out, int src)
{
    const float* __restrict__ nodes = src ? g_nodesB : g_nodesA;
    __shared__ float sA[128];
    __shared__ float sB[128];
    __shared__ int sred[128];
    int b = blockIdx.x, h = threadIdx.x;

    int v = 0;
    for (int i = h; i < b; i += 128) v += num_atoms[i];
    sred[h] = v;
    __syncthreads();
    for (int off = 64; off > 0; off >>= 1) {
        if (h < off) sred[h] += sred[h + off];
        __syncthreads();
    }
    int start = sred[0];
    int cnt = num_atoms[b];

    float s = 0.f;
    for (int a = 0; a < cnt; a++) s += nodes[(size_t)(start + a) * 128 + h];
    sA[h] = softplusf_(s / (float)cnt);
    __syncthreads();
    float t = fc1b[h];
    for (int k = 0; k < 128; k++) t = fmaf(sA[k], fc1W[k * 128 + h], t);
    sB[h] = softplusf_(t) * outW[h];
    __syncthreads();
    for (int off = 64; off > 0; off >>= 1) {
        if (h < off) sB[h] += sB[h + off];
        __syncthreads();
    }
    if (h == 0) out[b] = sB[0] + outb[0];
}

// ---------------- launch ----------------
extern "C" void kernel_launch(void* const* d_in, const int* in_sizes, int n_in,
                              void* d_out, int out_size)
{
    const float* ae      = (const float*)d_in[0];
    const float* che_fea = (const float*)d_in[1];
    const void*  p2      = d_in[2];
    const void*  p3      = d_in[3];
    const int*   vdw_idx = (const int*)d_in[4];
    const int*   natoms  = (const int*)d_in[5];
    const float* embW    = (const float*)d_in[6];
    const float* embB    = (const float*)d_in[7];
    const float* cheFW   = (const float*)d_in[8];
    const float* cheFb   = (const float*)d_in[9];
    const float* cheGW   = (const float*)d_in[10];
    const float* cheGb   = (const float*)d_in[11];
    const float* vdwFW   = (const float*)d_in[12];
    const float* vdwFb   = (const float*)d_in[13];
    const float* vdwGW   = (const float*)d_in[14];
    const float* vdwGb   = (const float*)d_in[15];
    const float* fc1W    = (const float*)d_in[16];
    const float* fc1b    = (const float*)d_in[17];
    const float* outW    = (const float*)d_in[18];
    const float* outb    = (const float*)d_in[19];

    prep_kernel<<<126 + 1536 + 625, 256>>>((const unsigned*)p2, ae, embW, embB,
                                           cheFW, cheFb, cheGW, cheGb,
                                           vdwFW, vdwFb, vdwGW, vdwGb);
    table16_kernel<<<dim3(KNOT, 6), 128>>>();

    int src = 0;
    for (int i = 0; i < 3; i++) {
        gemm_kernel<<<dim3((NPTS + 127) / 128, 8), 256>>>(src, i);
        conv_kernel<<<NPTS / NBLK, 128>>>(che_fea, (const float*)p2, (const float*)p3,
                                          (const int*)p2, (const int*)p3, vdw_idx, src, i);
        src ^= 1;
    }
    pool_kernel<<<BCRY, 128>>>(natoms, fc1W, fc1b, outW, outb, (float*)d_out, src);
}

// round 9
// speedup vs baseline: 1.3880x; 1.1766x over previous
#include <cuda_runtime.h>
#include <cuda_fp16.h>
#include <cstdint>

// ---------------- problem constants ----------------
#define NPTS 20000
#define MNBR 20
#define ERBF 20
#define HDIM 128
#define BCRY 200
#define NBLK 8
#define PI_F 3.14159265358979f
#define KNOT 4096
#define DMAX_CHE 8.81f
#define DMAX_VDW 13.21f

typedef unsigned long long u64;

// ---------------- device scratch ----------------
__device__ int   g_order;
__device__ float g_nodesA[NPTS * HDIM];
__device__ float g_nodesB[NPTS * HDIM];
__device__ __half2 g_STh[(size_t)NPTS * 512];            // [S_che|T_che|S_vdw|T_vdw] x 128 half2 (filt,core)
__device__ float g_Wcat[3 * 131072];
__device__ float g_We[3 * 2 * ERBF * 256];
__device__ float g_be[3 * 2 * 256];
__device__ uint2 g_tab16[(size_t)3 * 2 * KNOT * 128];    // packed fp16: {f_j,c_j,f_j+1,c_j+1} per (j,h)

// ---------------- f32x2 packed math ----------------
__device__ __forceinline__ u64 pk2(float lo, float hi) {
    u64 r; asm("mov.b64 %0, {%1,%2};" : "=l"(r) : "f"(lo), "f"(hi)); return r;
}
__device__ __forceinline__ void upk2(u64 v, float& lo, float& hi) {
    asm("mov.b64 {%0,%1}, %2;" : "=f"(lo), "=f"(hi) : "l"(v));
}
__device__ __forceinline__ u64 fma2(u64 a, u64 b, u64 c) {
    u64 d; asm("fma.rn.f32x2 %0, %1, %2, %3;" : "=l"(d) : "l"(a), "l"(b), "l"(c)); return d;
}

// ---------------- activations ----------------
__device__ __forceinline__ float softplusf_(float x) {
    return fmaxf(x, 0.f) + __logf(1.f + __expf(-fabsf(x)));
}
__device__ __forceinline__ float gatef_(float f, float c) {
    float t;
    asm("tanh.approx.f32 %0, %1;" : "=f"(t) : "f"(0.5f * f));
    float sig = fmaf(0.5f, t, 0.5f);
    return sig * softplusf_(c);
}

// ---------------- 1: merged prep: detect + folded edge weights + Wcat + embed ----------------
__global__ __launch_bounds__(256) void prep_kernel(
    const unsigned* __restrict__ p2u,
    const float* __restrict__ ae, const float* __restrict__ embW, const float* __restrict__ embB,
    const float* __restrict__ cheFW, const float* __restrict__ cheFb,
    const float* __restrict__ cheGW, const float* __restrict__ cheGb,
    const float* __restrict__ vdwFW, const float* __restrict__ vdwFb,
    const float* __restrict__ vdwGW, const float* __restrict__ vdwGb)
{
    int bid = blockIdx.x;
    int tid = threadIdx.x;
    if (bid == 0 && tid == 0) g_order = (p2u[0] > 1000000u) ? 1 : 0;

    if (bid < 126) {
        int layer = bid / 42, rem = bid % 42;
        int half = rem / 21, k = rem % 21;
        const float* fW = (half ? vdwFW : cheFW) + layer * 2560;
        const float* fb = (half ? vdwFb : cheFb) + layer * 128;
        const float* gW = (half ? vdwGW : cheGW) + (size_t)layer * 98304;
        const float* gb = (half ? vdwGb : cheGb) + layer * 256;
        float* We = g_We + (layer * 2 + half) * 5120;
        float* be = g_be + (layer * 2 + half) * 256;
        int c = tid;
        if (k < ERBF) {
            float s = 0.f;
            for (int hh = 0; hh < 128; hh++) s = fmaf(fW[k * 128 + hh], gW[(size_t)(128 + hh) * 256 + c], s);
            We[k * 256 + c] = s;
        } else {
            float s = gb[c];
            for (int hh = 0; hh < 128; hh++) s = fmaf(fb[hh], gW[(size_t)(128 + hh) * 256 + c], s);
            be[c] = s;
        }
    } else if (bid < 126 + 1536) {
        int idx = (bid - 126) * 256 + tid;             // [0, 393216)
        int layer = idx >> 17;
        int within = idx & 131071;
        int k = within >> 10;
        int c = within & 1023;
        int region = c >> 8;                           // 0 S_che, 1 T_che, 2 S_vdw, 3 T_vdw
        int cc = c & 255;
        int h = cc >> 1, p = cc & 1;                   // p=0 filt, p=1 core
        const float* gW = ((region < 2) ? cheGW : vdwGW) + (size_t)layer * 98304;
        int row = ((region & 1) ? 256 : 0) + k;
        g_Wcat[idx] = gW[(size_t)row * 256 + p * 128 + h];
    } else {
        __shared__ float sW[13 * 128];
        __shared__ float sa[32 * 13];
        int h = tid & 127, grp = tid >> 7;
        int n0 = (bid - (126 + 1536)) * 32;
        for (int i = tid; i < 13 * 128; i += 256) sW[i] = embW[i];
        for (int i = tid; i < 32 * 13; i += 256) sa[i] = ae[n0 * 13 + i];
        float bb = embB[h];
        __syncthreads();
#pragma unroll
        for (int nn = 0; nn < 16; nn++) {
            int ln = grp * 16 + nn;
            float s = bb;
#pragma unroll
            for (int k = 0; k < 13; k++) s = fmaf(sa[ln * 13 + k], sW[k * 128 + h], s);
            g_nodesA[(size_t)(n0 + ln) * 128 + h] = s;
        }
    }
}

// ---------------- 2: edge lookup tables (Chebyshev) -> packed fp16 pairs directly ----------------
__global__ __launch_bounds__(128) void table16_kernel()
{
    int j = blockIdx.x, lh = blockIdx.y, half = lh & 1, h = threadIdx.x;
    const float* We = g_We + lh * 5120;
    float bef = g_be[lh * 256 + h];
    float bec = g_be[lh * 256 + 128 + h];
    float cut  = half ? 12.f : 8.f;
    float dmax = half ? DMAX_VDW : DMAX_CHE;
    float step = dmax / (float)(KNOT - 3);
    int j1 = (j + 1 < KNOT) ? (j + 1) : (KNOT - 1);
    float d0 = (float)j * step, d1 = (float)j1 * step;

    float x0 = d0 * (PI_F / cut), x1 = d1 * (PI_F / cut);
    float sn_0 = sinf(x0), cs_0 = cosf(x0);
    float sn_1 = sinf(x1), cs_1 = cosf(x1);
    float coef0 = (d0 < cut && d0 > 1e-6f) ? 0.5f * (cs_0 + 1.f) / d0 : 0.f;
    float coef1 = (d1 < cut && d1 > 1e-6f) ? 0.5f * (cs_1 + 1.f) / d1 : 0.f;
    float c20 = 2.f * cs_0, c21 = 2.f * cs_1;
    float sk0 = sn_0, skm0 = 0.f, sk1 = sn_1, skm1 = 0.f;
    float f0 = bef, c0 = bec, f1 = bef, c1 = bec;
#pragma unroll
    for (int k = 0; k < ERBF; k++) {
        float wf = We[k * 256 + h], wc = We[k * 256 + 128 + h];
        float r0 = sk0 * coef0, r1 = sk1 * coef1;
        f0 = fmaf(r0, wf, f0); c0 = fmaf(r0, wc, c0);
        f1 = fmaf(r1, wf, f1); c1 = fmaf(r1, wc, c1);
        float t0 = fmaf(c20, sk0, -skm0); skm0 = sk0; sk0 = t0;
        float t1 = fmaf(c21, sk1, -skm1); skm1 = sk1; sk1 = t1;
    }
    __half2 a = __floats2half2_rn(f0, c0);
    __half2 b = __floats2half2_rn(f1, c1);
    uint2 v;
    v.x = *(unsigned*)&a;
    v.y = *(unsigned*)&b;
    g_tab16[((size_t)lh * KNOT + j) * 128 + h] = v;
}

// ---------------- 3: ST GEMM  [N,128]x[128,1024], f32x2, double-buffered, fp16 epilogue ----------------
__global__ __launch_bounds__(256, 2) void gemm_kernel(int src, int layer)
{
    const float* __restrict__ A = src ? g_nodesB : g_nodesA;
    const float* __restrict__ Bm = g_Wcat + (size_t)layer * 131072;

    __shared__ __align__(16) float As[2][8][128];
    __shared__ __align__(16) float Bs[2][8][128];

    int r0 = blockIdx.x * 128;
    int c0 = blockIdx.y * 128;
    int tid = threadIdx.x;
    int tx = tid & 15, ty = tid >> 4;

    u64 acc[8][4];
#pragma unroll
    for (int i = 0; i < 8; i++)
#pragma unroll
        for (int j = 0; j < 4; j++) acc[i][j] = pk2(0.f, 0.f);

    int arow = tid >> 1;
    int acol = (tid & 1) * 4;
    int brow = tid >> 5;
    int bcol = (tid & 31) * 4;
    int gr = r0 + arow;
    const float* Aptr = A + (size_t)gr * 128 + acol;
    const float* Bptr = Bm + (size_t)brow * 1024 + c0 + bcol;

    float4 av = make_float4(0.f, 0.f, 0.f, 0.f);
    if (gr < NPTS) av = *(const float4*)Aptr;
    float4 bv = *(const float4*)Bptr;
    As[0][acol + 0][arow] = av.x;
    As[0][acol + 1][arow] = av.y;
    As[0][acol + 2][arow] = av.z;
    As[0][acol + 3][arow] = av.w;
    *(float4*)&Bs[0][brow][bcol] = bv;
    __syncthreads();

#pragma unroll 1
    for (int t = 0; t < 16; t++) {
        int cur = t & 1;
        float4 avn = make_float4(0.f, 0.f, 0.f, 0.f), bvn;
        if (t < 15) {
            if (gr < NPTS) avn = *(const float4*)(Aptr + 8 * (t + 1));
            bvn = *(const float4*)(Bptr + (size_t)8 * (t + 1) * 1024);
        }
#pragma unroll
        for (int k = 0; k < 8; k++) {
            ulonglong2 bb0 = *(const ulonglong2*)&Bs[cur][k][tx * 8];
            ulonglong2 bb1 = *(const ulonglong2*)&Bs[cur][k][tx * 8 + 4];
#pragma unroll
            for (int i = 0; i < 8; i++) {
                float a_ = As[cur][k][ty * 8 + i];
                u64 a2 = pk2(a_, a_);
                acc[i][0] = fma2(a2, bb0.x, acc[i][0]);
                acc[i][1] = fma2(a2, bb0.y, acc[i][1]);
                acc[i][2] = fma2(a2, bb1.x, acc[i][2]);
                acc[i][3] = fma2(a2, bb1.y, acc[i][3]);
            }
        }
        if (t < 15) {
            As[cur ^ 1][acol + 0][arow] = avn.x;
            As[cur ^ 1][acol + 1][arow] = avn.y;
            As[cur ^ 1][acol + 2][arow] = avn.z;
            As[cur ^ 1][acol + 3][arow] = avn.w;
            *(float4*)&Bs[cur ^ 1][brow][bcol] = bvn;
        }
        __syncthreads();
    }

#pragma unroll
    for (int i = 0; i < 8; i++) {
        int gr2 = r0 + ty * 8 + i;
        if (gr2 < NPTS) {
            float x0, x1, x2, x3, x4, x5, x6, x7;
            upk2(acc[i][0], x0, x1);
            upk2(acc[i][1], x2, x3);
            upk2(acc[i][2], x4, x5);
            upk2(acc[i][3], x6, x7);
            __half2 h0 = __floats2half2_rn(x0, x1);
            __half2 h1 = __floats2half2_rn(x2, x3);
            __half2 h2 = __floats2half2_rn(x4, x5);
            __half2 h3 = __floats2half2_rn(x6, x7);
            uint4 v;
            v.x = *(unsigned*)&h0; v.y = *(unsigned*)&h1;
            v.z = *(unsigned*)&h2; v.w = *(unsigned*)&h3;
            *(uint4*)(g_STh + (size_t)gr2 * 512 + (c0 >> 1) + tx * 4) = v;
        }
    }
}

// ---------------- 4: fused gated conv — packed metadata, half2 math, 2-node pipelines ----------------
__global__ __launch_bounds__(128) void conv_kernel(
    const float* __restrict__ che_fea, const float* __restrict__ p2f, const float* __restrict__ p3f,
    const int* __restrict__ p2i, const int* __restrict__ p3i,
    const int* __restrict__ vdw_idx, int src, int layer)
{
    const int* che_idx = g_order ? p3i : p2i;
    const float* vdw_fea = g_order ? p2f : p3f;
    const float* __restrict__ nodes = src ? g_nodesB : g_nodesA;
    float* __restrict__ nodes_out = src ? g_nodesA : g_nodesB;

    __shared__ __align__(16) uint4 s_pk[NBLK * MNBR];   // {idx_byteoff, knot_byteoff, fr_half2, 0}
    __shared__ float s_acc[NBLK * 128];

    int h = threadIdx.x;
    int n0 = blockIdx.x * NBLK;
#pragma unroll
    for (int i = 0; i < NBLK; i++) s_acc[i * 128 + h] = 0.f;

#pragma unroll 1
    for (int half = 0; half < 2; half++) {
        const char* tbb = (const char*)(g_tab16 + (size_t)(layer * 2 + half) * KNOT * 128) + h * 8;
        const float* feap = half ? vdw_fea : che_fea;
        const int* idxp = half ? vdw_idx : che_idx;
        float scale = half ? ((float)(KNOT - 3) / DMAX_VDW) : ((float)(KNOT - 3) / DMAX_CHE);
        const char* stb = (const char*)g_STh + ((half ? 384 : 128) + h) * 4;  // T region byte base
        int soff = (half ? 256 : 0) + h;                                       // S region half2 index

        __syncthreads();
        for (int i = h; i < NBLK * MNBR; i += 128) {
            float d = feap[n0 * MNBR + i];
            float u = fminf(d * scale, (float)(KNOT - 3));
            float jf = floorf(u);
            float fr = u - jf;
            __half2 frh = __float2half2_rn(fr);
            s_pk[i] = make_uint4((unsigned)idxp[n0 * MNBR + i] * 2048u,
                                 (unsigned)jf * 1024u,
                                 *(unsigned*)&frh, 0u);
        }
        __syncthreads();

#pragma unroll 1
        for (int nn = 0; nn < NBLK; nn += 2) {
            int nA = n0 + nn, nB = nA + 1;
            int iA = nn * MNBR, iB = iA + MNBR;
            float2 svA = __half22float2(g_STh[(size_t)nA * 512 + soff]);
            float2 svB = __half22float2(g_STh[(size_t)nB * 512 + soff]);

            uint4 pA0 = s_pk[iA],     pA1 = s_pk[iA + 1];
            uint4 pB0 = s_pk[iB],     pB1 = s_pk[iB + 1];
            __half2 tgA0 = *(const __half2*)(stb + pA0.x);
            uint2   tpA0 = *(const uint2*)(tbb + pA0.y);
            __half2 tgA1 = *(const __half2*)(stb + pA1.x);
            uint2   tpA1 = *(const uint2*)(tbb + pA1.y);
            __half2 tgB0 = *(const __half2*)(stb + pB0.x);
            uint2   tpB0 = *(const uint2*)(tbb + pB0.y);
            __half2 tgB1 = *(const __half2*)(stb + pB1.x);
            uint2   tpB1 = *(const uint2*)(tbb + pB1.y);
            unsigned frA0 = pA0.z, frA1 = pA1.z, frB0 = pB0.z, frB1 = pB1.z;

            float aA = 0.f, aB = 0.f;
#pragma unroll 1
            for (int m = 0; m < MNBR; m++) {
                int mp = (m + 2 < MNBR) ? (m + 2) : (MNBR - 1);
                __half2 tgAc = tgA0; uint2 tpAc = tpA0; unsigned frAc = frA0;
                __half2 tgBc = tgB0; uint2 tpBc = tpB0; unsigned frBc = frB0;
                tgA0 = tgA1; tpA0 = tpA1; frA0 = frA1;
                tgB0 = tgB1; tpB0 = tpB1; frB0 = frB1;
                uint4 pA = s_pk[iA + mp];
                uint4 pB = s_pk[iB + mp];
                tgA1 = *(const __half2*)(stb + pA.x);
                tpA1 = *(const uint2*)(tbb + pA.y);
                frA1 = pA.z;
                tgB1 = *(const __half2*)(stb + pB.x);
                tpB1 = *(const uint2*)(tbb + pB.y);
                frB1 = pB.z;

                {
                    __half2 t0 = *(__half2*)&tpAc.x, t1 = *(__half2*)&tpAc.y;
                    __half2 e = __hfma2(*(__half2*)&frAc, __hsub2(t1, t0), t0);
                    float2 g2 = __half22float2(__hadd2(tgAc, e));
                    aA += gatef_(svA.x + g2.x, svA.y + g2.y);
                }
                {
                    __half2 t0 = *(__half2*)&tpBc.x, t1 = *(__half2*)&tpBc.y;
                    __half2 e = __hfma2(*(__half2*)&frBc, __hsub2(t1, t0), t0);
                    float2 g2 = __half22float2(__hadd2(tgBc, e));
                    aB += gatef_(svB.x + g2.x, svB.y + g2.y);
                }
            }
            s_acc[nn * 128 + h]       += aA;
            s_acc[(nn + 1) * 128 + h] += aB;
        }
    }
#pragma unroll
    for (int nn = 0; nn < NBLK; nn++) {
        int n = n0 + nn;
        float r = nodes[(size_t)n * 128 + h] + s_acc[nn * 128 + h];
        nodes_out[(size_t)n * 128 + h] = softplusf_(r);
    }
}

// ---------------- 5: pooling + MLP head ----------------
__global__ __launch_bounds__(128) void pool_kernel(
    const int* __restrict__ num_atoms,
    const float* __restrict__ fc1W, const float* __restrict__ fc1b,
    const float* __restrict__ outW, const float* __restrict__ outb,
    float* __restrict__ out, int src)
{
    const float* __restrict__ nodes = src ? g_nodesB : g_nodesA;
    __shared__ float sA[128];
    __shared__ float sB[128];
    __shared__ int sred[128];
    int b = blockIdx.x, h = threadIdx.x;

    int v = 0;
    for (int i = h; i < b; i += 128) v += num_atoms[i];
    sred[h] = v;
    __syncthreads();
    for (int off = 64; off > 0; off >>= 1) {
        if (h < off) sred[h] += sred[h + off];
        __syncthreads();
    }
    int start = sred[0];
    int cnt = num_atoms[b];

    float s = 0.f;
    for (int a = 0; a < cnt; a++) s += nodes[(size_t)(start + a) * 128 + h];
    sA[h] = softplusf_(s / (float)cnt);
    __syncthreads();
    float t = fc1b[h];
    for (int k = 0; k < 128; k++) t = fmaf(sA[k], fc1W[k * 128 + h], t);
    sB[h] = softplusf_(t) * outW[h];
    __syncthreads();
    for (int off = 64; off > 0; off >>= 1) {
        if (h < off) sB[h] += sB[h + off];
        __syncthreads();
    }
    if (h == 0) out[b] = sB[0] + outb[0];
}

// ---------------- launch ----------------
extern "C" void kernel_launch(void* const* d_in, const int* in_sizes, int n_in,
                              void* d_out, int out_size)
{
    const float* ae      = (const float*)d_in[0];
    const float* che_fea = (const float*)d_in[1];
    const void*  p2      = d_in[2];
    const void*  p3      = d_in[3];
    const int*   vdw_idx = (const int*)d_in[4];
    const int*   natoms  = (const int*)d_in[5];
    const float* embW    = (const float*)d_in[6];
    const float* embB    = (const float*)d_in[7];
    const float* cheFW   = (const float*)d_in[8];
    const float* cheFb   = (const float*)d_in[9];
    const float* cheGW   = (const float*)d_in[10];
    const float* cheGb   = (const float*)d_in[11];
    const float* vdwFW   = (const float*)d_in[12];
    const float* vdwFb   = (const float*)d_in[13];
    const float* vdwGW   = (const float*)d_in[14];
    const float* vdwGb   = (const float*)d_in[15];
    const float* fc1W    = (const float*)d_in[16];
    const float* fc1b    = (const float*)d_in[17];
    const float* outW    = (const float*)d_in[18];
    const float* outb    = (const float*)d_in[19];

    prep_kernel<<<126 + 1536 + 625, 256>>>((const unsigned*)p2, ae, embW, embB,
                                           cheFW, cheFb, cheGW, cheGb,
                                           vdwFW, vdwFb, vdwGW, vdwGb);
    table16_kernel<<<dim3(KNOT, 6), 128>>>();

    int src = 0;
    for (int i = 0; i < 3; i++) {
        gemm_kernel<<<dim3((NPTS + 127) / 128, 8), 256>>>(src, i);
        conv_kernel<<<NPTS / NBLK, 128>>>(che_fea, (const float*)p2, (const float*)p3,
                                          (const int*)p2, (const int*)p3, vdw_idx, src, i);
        src ^= 1;
    }
    pool_kernel<<<BCRY, 128>>>(natoms, fc1W, fc1b, outW, outb, (float*)d_out, src);
}

// round 10
// speedup vs baseline: 1.5460x; 1.1139x over previous
#include <cuda_runtime.h>
#include <cuda_fp16.h>
#include <cstdint>

// ---------------- problem constants ----------------
#define NPTS 20000
#define MNBR 20
#define ERBF 20
#define HDIM 128
#define BCRY 200
#define NBLK 8
#define PI_F 3.14159265358979f
#define KNOT 4096
#define DMAX_CHE 8.81f
#define DMAX_VDW 13.21f

typedef unsigned long long u64;

// ---------------- device scratch ----------------
__device__ int   g_order;
__device__ float g_nodesA[NPTS * HDIM];
__device__ float g_nodesB[NPTS * HDIM];
__device__ __half2 g_STh[(size_t)NPTS * 512];            // [S_che|T_che|S_vdw|T_vdw] x 128 half2 (filt,core)
__device__ float g_Wcat[3 * 131072];
__device__ float g_We[3 * 2 * ERBF * 256];
__device__ float g_be[3 * 2 * 256];
__device__ uint2 g_tab16[(size_t)3 * 2 * KNOT * 128];    // packed fp16: {f_j,c_j,f_j+1,c_j+1} per (j,h)

// ---------------- f32x2 packed math ----------------
__device__ __forceinline__ u64 pk2(float lo, float hi) {
    u64 r; asm("mov.b64 %0, {%1,%2};" : "=l"(r) : "f"(lo), "f"(hi)); return r;
}
__device__ __forceinline__ void upk2(u64 v, float& lo, float& hi) {
    asm("mov.b64 {%0,%1}, %2;" : "=f"(lo), "=f"(hi) : "l"(v));
}
__device__ __forceinline__ u64 fma2(u64 a, u64 b, u64 c) {
    u64 d; asm("fma.rn.f32x2 %0, %1, %2, %3;" : "=l"(d) : "l"(a), "l"(b), "l"(c)); return d;
}

// ---------------- activations ----------------
__device__ __forceinline__ float softplusf_(float x) {
    return fmaxf(x, 0.f) + __logf(1.f + __expf(-fabsf(x)));
}

// gate for two nodes at once: g2A=(fA,cA), g2B=(fB,cB) in half2.
// sigmoid via tanh.approx.f16x2, exp via ex2.approx.f16x2, log kept f32.
__device__ __forceinline__ void gate2_(__half2 g2A, __half2 g2B, float& aA, float& aB)
{
    __half2 fAB = __halves2half2(__low2half(g2A), __low2half(g2B));
    __half2 cAB = __halves2half2(__high2half(g2A), __high2half(g2B));
    const __half2 h_half = __float2half2_rn(0.5f);
    __half2 th, u;
    __half2 harg = __hmul2(fAB, h_half);
    asm("tanh.approx.f16x2 %0, %1;" : "=r"(*(unsigned*)&th) : "r"(*(unsigned*)&harg));
    __half2 sig = __hfma2(th, h_half, h_half);
    __half2 relu = __hmax2(cAB, __float2half2_rn(0.f));
    __half2 earg = __hmul2(__habs2(cAB), __float2half2_rn(-1.44269504f));
    asm("ex2.approx.f16x2 %0, %1;" : "=r"(*(unsigned*)&u) : "r"(*(unsigned*)&earg));
    float2 uf = __half22float2(u);
    float2 rf = __half22float2(relu);
    float2 sgf = __half22float2(sig);
    float lx = __logf(1.f + uf.x);
    float ly = __logf(1.f + uf.y);
    aA = fmaf(sgf.x, rf.x + lx, aA);
    aB = fmaf(sgf.y, rf.y + ly, aB);
}

// ---------------- 1: merged prep: detect + folded edge weights + Wcat + embed ----------------
__global__ __launch_bounds__(256) void prep_kernel(
    const unsigned* __restrict__ p2u,
    const float* __restrict__ ae, const float* __restrict__ embW, const float* __restrict__ embB,
    const float* __restrict__ cheFW, const float* __restrict__ cheFb,
    const float* __restrict__ cheGW, const float* __restrict__ cheGb,
    const float* __restrict__ vdwFW, const float* __restrict__ vdwFb,
    const float* __restrict__ vdwGW, const float* __restrict__ vdwGb)
{
    int bid = blockIdx.x;
    int tid = threadIdx.x;
    if (bid == 0 && tid == 0) g_order = (p2u[0] > 1000000u) ? 1 : 0;

    if (bid < 126) {
        int layer = bid / 42, rem = bid % 42;
        int half = rem / 21, k = rem % 21;
        const float* fW = (half ? vdwFW : cheFW) + layer * 2560;
        const float* fb = (half ? vdwFb : cheFb) + layer * 128;
        const float* gW = (half ? vdwGW : cheGW) + (size_t)layer * 98304;
        const float* gb = (half ? vdwGb : cheGb) + layer * 256;
        float* We = g_We + (layer * 2 + half) * 5120;
        float* be = g_be + (layer * 2 + half) * 256;
        int c = tid;
        if (k < ERBF) {
            float s = 0.f;
            for (int hh = 0; hh < 128; hh++) s = fmaf(fW[k * 128 + hh], gW[(size_t)(128 + hh) * 256 + c], s);
            We[k * 256 + c] = s;
        } else {
            float s = gb[c];
            for (int hh = 0; hh < 128; hh++) s = fmaf(fb[hh], gW[(size_t)(128 + hh) * 256 + c], s);
            be[c] = s;
        }
    } else if (bid < 126 + 1536) {
        int idx = (bid - 126) * 256 + tid;             // [0, 393216)
        int layer = idx >> 17;
        int within = idx & 131071;
        int k = within >> 10;
        int c = within & 1023;
        int region = c >> 8;                           // 0 S_che, 1 T_che, 2 S_vdw, 3 T_vdw
        int cc = c & 255;
        int h = cc >> 1, p = cc & 1;                   // p=0 filt, p=1 core
        const float* gW = ((region < 2) ? cheGW : vdwGW) + (size_t)layer * 98304;
        int row = ((region & 1) ? 256 : 0) + k;
        g_Wcat[idx] = gW[(size_t)row * 256 + p * 128 + h];
    } else {
        __shared__ float sW[13 * 128];
        __shared__ float sa[32 * 13];
        int h = tid & 127, grp = tid >> 7;
        int n0 = (bid - (126 + 1536)) * 32;
        for (int i = tid; i < 13 * 128; i += 256) sW[i] = embW[i];
        for (int i = tid; i < 32 * 13; i += 256) sa[i] = ae[n0 * 13 + i];
        float bb = embB[h];
        __syncthreads();
#pragma unroll
        for (int nn = 0; nn < 16; nn++) {
            int ln = grp * 16 + nn;
            float s = bb;
#pragma unroll
            for (int k = 0; k < 13; k++) s = fmaf(sa[ln * 13 + k], sW[k * 128 + h], s);
            g_nodesA[(size_t)(n0 + ln) * 128 + h] = s;
        }
    }
}

// ---------------- 2: edge lookup tables (Chebyshev) -> packed fp16 pairs directly ----------------
__global__ __launch_bounds__(128) void table16_kernel()
{
    int j = blockIdx.x, lh = blockIdx.y, half = lh & 1, h = threadIdx.x;
    const float* We = g_We + lh * 5120;
    float bef = g_be[lh * 256 + h];
    float bec = g_be[lh * 256 + 128 + h];
    float cut  = half ? 12.f : 8.f;
    float dmax = half ? DMAX_VDW : DMAX_CHE;
    float step = dmax / (float)(KNOT - 3);
    int j1 = (j + 1 < KNOT) ? (j + 1) : (KNOT - 1);
    float d0 = (float)j * step, d1 = (float)j1 * step;

    float x0 = d0 * (PI_F / cut), x1 = d1 * (PI_F / cut);
    float sn_0 = sinf(x0), cs_0 = cosf(x0);
    float sn_1 = sinf(x1), cs_1 = cosf(x1);
    float coef0 = (d0 < cut && d0 > 1e-6f) ? 0.5f * (cs_0 + 1.f) / d0 : 0.f;
    float coef1 = (d1 < cut && d1 > 1e-6f) ? 0.5f * (cs_1 + 1.f) / d1 : 0.f;
    float c20 = 2.f * cs_0, c21 = 2.f * cs_1;
    float sk0 = sn_0, skm0 = 0.f, sk1 = sn_1, skm1 = 0.f;
    float f0 = bef, c0 = bec, f1 = bef, c1 = bec;
#pragma unroll
    for (int k = 0; k < ERBF; k++) {
        float wf = We[k * 256 + h], wc = We[k * 256 + 128 + h];
        float r0 = sk0 * coef0, r1 = sk1 * coef1;
        f0 = fmaf(r0, wf, f0); c0 = fmaf(r0, wc, c0);
        f1 = fmaf(r1, wf, f1); c1 = fmaf(r1, wc, c1);
        float t0 = fmaf(c20, sk0, -skm0); skm0 = sk0; sk0 = t0;
        float t1 = fmaf(c21, sk1, -skm1); skm1 = sk1; sk1 = t1;
    }
    __half2 a = __floats2half2_rn(f0, c0);
    __half2 b = __floats2half2_rn(f1, c1);
    uint2 v;
    v.x = *(unsigned*)&a;
    v.y = *(unsigned*)&b;
    g_tab16[((size_t)lh * KNOT + j) * 128 + h] = v;
}

// ---------------- 3: ST GEMM  [N,128]x[128,1024], f32x2, double-buffered, fp16 epilogue ----------------
__global__ __launch_bounds__(256, 2) void gemm_kernel(int src, int layer)
{
    const float* __restrict__ A = src ? g_nodesB : g_nodesA;
    const float* __restrict__ Bm = g_Wcat + (size_t)layer * 131072;

    __shared__ __align__(16) float As[2][8][128];
    __shared__ __align__(16) float Bs[2][8][128];

    int r0 = blockIdx.x * 128;
    int c0 = blockIdx.y * 128;
    int tid = threadIdx.x;
    int tx = tid & 15, ty = tid >> 4;

    u64 acc[8][4];
#pragma unroll
    for (int i = 0; i < 8; i++)
#pragma unroll
        for (int j = 0; j < 4; j++) acc[i][j] = pk2(0.f, 0.f);

    int arow = tid >> 1;
    int acol = (tid & 1) * 4;
    int brow = tid >> 5;
    int bcol = (tid & 31) * 4;
    int gr = r0 + arow;
    const float* Aptr = A + (size_t)gr * 128 + acol;
    const float* Bptr = Bm + (size_t)brow * 1024 + c0 + bcol;

    float4 av = make_float4(0.f, 0.f, 0.f, 0.f);
    if (gr < NPTS) av = *(const float4*)Aptr;
    float4 bv = *(const float4*)Bptr;
    As[0][acol + 0][arow] = av.x;
    As[0][acol + 1][arow] = av.y;
    As[0][acol + 2][arow] = av.z;
    As[0][acol + 3][arow] = av.w;
    *(float4*)&Bs[0][brow][bcol] = bv;
    __syncthreads();

#pragma unroll 1
    for (int t = 0; t < 16; t++) {
        int cur = t & 1;
        float4 avn = make_float4(0.f, 0.f, 0.f, 0.f), bvn;
        if (t < 15) {
            if (gr < NPTS) avn = *(const float4*)(Aptr + 8 * (t + 1));
            bvn = *(const float4*)(Bptr + (size_t)8 * (t + 1) * 1024);
        }
#pragma unroll
        for (int k = 0; k < 8; k++) {
            ulonglong2 bb0 = *(const ulonglong2*)&Bs[cur][k][tx * 8];
            ulonglong2 bb1 = *(const ulonglong2*)&Bs[cur][k][tx * 8 + 4];
#pragma unroll
            for (int i = 0; i < 8; i++) {
                float a_ = As[cur][k][ty * 8 + i];
                u64 a2 = pk2(a_, a_);
                acc[i][0] = fma2(a2, bb0.x, acc[i][0]);
                acc[i][1] = fma2(a2, bb0.y, acc[i][1]);
                acc[i][2] = fma2(a2, bb1.x, acc[i][2]);
                acc[i][3] = fma2(a2, bb1.y, acc[i][3]);
            }
        }
        if (t < 15) {
            As[cur ^ 1][acol + 0][arow] = avn.x;
            As[cur ^ 1][acol + 1][arow] = avn.y;
            As[cur ^ 1][acol + 2][arow] = avn.z;
            As[cur ^ 1][acol + 3][arow] = avn.w;
            *(float4*)&Bs[cur ^ 1][brow][bcol] = bvn;
        }
        __syncthreads();
    }

#pragma unroll
    for (int i = 0; i < 8; i++) {
        int gr2 = r0 + ty * 8 + i;
        if (gr2 < NPTS) {
            float x0, x1, x2, x3, x4, x5, x6, x7;
            upk2(acc[i][0], x0, x1);
            upk2(acc[i][1], x2, x3);
            upk2(acc[i][2], x4, x5);
            upk2(acc[i][3], x6, x7);
            __half2 h0 = __floats2half2_rn(x0, x1);
            __half2 h1 = __floats2half2_rn(x2, x3);
            __half2 h2 = __floats2half2_rn(x4, x5);
            __half2 h3 = __floats2half2_rn(x6, x7);
            uint4 v;
            v.x = *(unsigned*)&h0; v.y = *(unsigned*)&h1;
            v.z = *(unsigned*)&h2; v.w = *(unsigned*)&h3;
            *(uint4*)(g_STh + (size_t)gr2 * 512 + (c0 >> 1) + tx * 4) = v;
        }
    }
}

// ---------------- 4: fused gated conv — full unroll, f16x2 gate, 2-node pipelines ----------------
__global__ __launch_bounds__(128) void conv_kernel(
    const float* __restrict__ che_fea, const float* __restrict__ p2f, const float* __restrict__ p3f,
    const int* __restrict__ p2i, const int* __restrict__ p3i,
    const int* __restrict__ vdw_idx, int src, int layer)
{
    const int* che_idx = g_order ? p3i : p2i;
    const float* vdw_fea = g_order ? p2f : p3f;
    const float* __restrict__ nodes = src ? g_nodesB : g_nodesA;
    float* __restrict__ nodes_out = src ? g_nodesA : g_nodesB;

    __shared__ __align__(16) uint4 s_pk[NBLK * MNBR];   // {idx_byteoff, knot_byteoff, fr_half2, 0}
    __shared__ float s_acc[NBLK * 128];

    int h = threadIdx.x;
    int n0 = blockIdx.x * NBLK;
#pragma unroll
    for (int i = 0; i < NBLK; i++) s_acc[i * 128 + h] = 0.f;

#pragma unroll 1
    for (int half = 0; half < 2; half++) {
        const char* tbb = (const char*)(g_tab16 + (size_t)(layer * 2 + half) * KNOT * 128) + h * 8;
        const float* feap = half ? vdw_fea : che_fea;
        const int* idxp = half ? vdw_idx : che_idx;
        float scale = half ? ((float)(KNOT - 3) / DMAX_VDW) : ((float)(KNOT - 3) / DMAX_CHE);
        const char* stb = (const char*)g_STh + ((half ? 384 : 128) + h) * 4;  // T region byte base
        int soff = (half ? 256 : 0) + h;                                       // S region half2 index

        __syncthreads();
        for (int i = h; i < NBLK * MNBR; i += 128) {
            float d = feap[n0 * MNBR + i];
            float u = fminf(d * scale, (float)(KNOT - 3));
            float jf = floorf(u);
            float fr = u - jf;
            __half2 frh = __float2half2_rn(fr);
            s_pk[i] = make_uint4((unsigned)idxp[n0 * MNBR + i] * 2048u,
                                 (unsigned)jf * 1024u,
                                 *(unsigned*)&frh, 0u);
        }
        __syncthreads();

#pragma unroll 1
        for (int nn = 0; nn < NBLK; nn += 2) {
            int nA = n0 + nn, nB = nA + 1;
            int iA = nn * MNBR, iB = iA + MNBR;
            __half2 svA = g_STh[(size_t)nA * 512 + soff];
            __half2 svB = g_STh[(size_t)nB * 512 + soff];

            __half2 tgA[2], tgB[2];
            uint2   tpA[2], tpB[2];
            unsigned frA[2], frB[2];
#pragma unroll
            for (int s = 0; s < 2; s++) {
                uint4 pA = s_pk[iA + s];
                uint4 pB = s_pk[iB + s];
                tgA[s] = *(const __half2*)(stb + pA.x);
                tpA[s] = *(const uint2*)(tbb + pA.y);
                frA[s] = pA.z;
                tgB[s] = *(const __half2*)(stb + pB.x);
                tpB[s] = *(const uint2*)(tbb + pB.y);
                frB[s] = pB.z;
            }

            float aA = 0.f, aB = 0.f;
#pragma unroll
            for (int m = 0; m < MNBR; m++) {
                int s = m & 1;
                __half2 tgAc = tgA[s]; uint2 tpAc = tpA[s]; unsigned frAc = frA[s];
                __half2 tgBc = tgB[s]; uint2 tpBc = tpB[s]; unsigned frBc = frB[s];
                if (m + 2 < MNBR) {
                    uint4 pA = s_pk[iA + m + 2];
                    uint4 pB = s_pk[iB + m + 2];
                    tgA[s] = *(const __half2*)(stb + pA.x);
                    tpA[s] = *(const uint2*)(tbb + pA.y);
                    frA[s] = pA.z;
                    tgB[s] = *(const __half2*)(stb + pB.x);
                    tpB[s] = *(const uint2*)(tbb + pB.y);
                    frB[s] = pB.z;
                }

                __half2 t0A = *(__half2*)&tpAc.x, t1A = *(__half2*)&tpAc.y;
                __half2 eA = __hfma2(*(__half2*)&frAc, __hsub2(t1A, t0A), t0A);
                __half2 g2A = __hadd2(__hadd2(svA, tgAc), eA);
                __half2 t0B = *(__half2*)&tpBc.x, t1B = *(__half2*)&tpBc.y;
                __half2 eB = __hfma2(*(__half2*)&frBc, __hsub2(t1B, t0B), t0B);
                __half2 g2B = __hadd2(__hadd2(svB, tgBc), eB);
                gate2_(g2A, g2B, aA, aB);
            }
            s_acc[nn * 128 + h]       += aA;
            s_acc[(nn + 1) * 128 + h] += aB;
        }
    }
#pragma unroll
    for (int nn = 0; nn < NBLK; nn++) {
        int n = n0 + nn;
        float r = nodes[(size_t)n * 128 + h] + s_acc[nn * 128 + h];
        nodes_out[(size_t)n * 128 + h] = softplusf_(r);
    }
}

// ---------------- 5: pooling + MLP head ----------------
__global__ __launch_bounds__(128) void pool_kernel(
    const int* __restrict__ num_atoms,
    const float* __restrict__ fc1W, const float* __restrict__ fc1b,
    const float* __restrict__ outW, const float* __restrict__ outb,
    float* __restrict__ out, int src)
{
    const float* __restrict__ nodes = src ? g_nodesB : g_nodesA;
    __shared__ float sA[128];
    __shared__ float sB[128];
    __shared__ int sred[128];
    int b = blockIdx.x, h = threadIdx.x;

    int v = 0;
    for (int i = h; i < b; i += 128) v += num_atoms[i];
    sred[h] = v;
    __syncthreads();
    for (int off = 64; off > 0; off >>= 1) {
        if (h < off) sred[h] += sred[h + off];
        __syncthreads();
    }
    int start = sred[0];
    int cnt = num_atoms[b];

    float s = 0.f;
    for (int a = 0; a < cnt; a++) s += nodes[(size_t)(start + a) * 128 + h];
    sA[h] = softplusf_(s / (float)cnt);
    __syncthreads();
    float t = fc1b[h];
    for (int k = 0; k < 128; k++) t = fmaf(sA[k], fc1W[k * 128 + h], t);
    sB[h] = softplusf_(t) * outW[h];
    __syncthreads();
    for (int off = 64; off > 0; off >>= 1) {
        if (h < off) sB[h] += sB[h + off];
        __syncthreads();
    }
    if (h == 0) out[b] = sB[0] + outb[0];
}

// ---------------- launch ----------------
extern "C" void kernel_launch(void* const* d_in, const int* in_sizes, int n_in,
                              void* d_out, int out_size)
{
    const float* ae      = (const float*)d_in[0];
    const float* che_fea = (const float*)d_in[1];
    const void*  p2      = d_in[2];
    const void*  p3      = d_in[3];
    const int*   vdw_idx = (const int*)d_in[4];
    const int*   natoms  = (const int*)d_in[5];
    const float* embW    = (const float*)d_in[6];
    const float* embB    = (const float*)d_in[7];
    const float* cheFW   = (const float*)d_in[8];
    const float* cheFb   = (const float*)d_in[9];
    const float* cheGW   = (const float*)d_in[10];
    const float* cheGb   = (const float*)d_in[11];
    const float* vdwFW   = (const float*)d_in[12];
    const float* vdwFb   = (const float*)d_in[13];
    const float* vdwGW   = (const float*)d_in[14];
    const float* vdwGb   = (const float*)d_in[15];
    const float* fc1W    = (const float*)d_in[16];
    const float* fc1b    = (const float*)d_in[17];
    const float* outW    = (const float*)d_in[18];
    const float* outb    = (const float*)d_in[19];

    prep_kernel<<<126 + 1536 + 625, 256>>>((const unsigned*)p2, ae, embW, embB,
                                           cheFW, cheFb, cheGW, cheGb,
                                           vdwFW, vdwFb, vdwGW, vdwGb);
    table16_kernel<<<dim3(KNOT, 6), 128>>>();

    int src = 0;
    for (int i = 0; i < 3; i++) {
        gemm_kernel<<<dim3((NPTS + 127) / 128, 8), 256>>>(src, i);
        conv_kernel<<<NPTS / NBLK, 128>>>(che_fea, (const float*)p2, (const float*)p3,
                                          (const int*)p2, (const int*)p3, vdw_idx, src, i);
        src ^= 1;
    }
    pool_kernel<<<BCRY, 128>>>(natoms, fc1W, fc1b, outW, outb, (float*)d_out, src);
}

// round 11
// speedup vs baseline: 2.0383x; 1.3184x over previous
#include <cuda_runtime.h>
#include <cuda_fp16.h>
#include <cuda_bf16.h>
#include <cstdint>

// ---------------- problem constants ----------------
#define NPTS 20000
#define NPAD 20096          // 157*128
#define MNBR 20
#define ERBF 20
#define HDIM 128
#define BCRY 200
#define NBLK 8
#define PI_F 3.14159265358979f
#define KNOT 4096
#define DMAX_CHE 8.81f
#define DMAX_VDW 13.21f

typedef unsigned long long u64;

// ---------------- device scratch ----------------
__device__ int   g_order;
__device__ float g_nodesA[NPTS * HDIM];
__device__ float g_nodesB[NPTS * HDIM];
__device__ __half2 g_STh[(size_t)NPTS * 512];            // [S_che|T_che|S_vdw|T_vdw] x 128 half2 (filt,core)
__device__ float g_We[3 * 2 * ERBF * 256];
__device__ float g_be[3 * 2 * 256];
__device__ uint2 g_tab16[(size_t)3 * 2 * KNOT * 128];    // packed fp16: {f_j,c_j,f_j+1,c_j+1} per (j,h)
// bf16 split operands for tensor-core GEMM
__device__ __align__(16) unsigned short g_Bh[3 * 131072];   // [layer][c(1024)][k(128)] n-major
__device__ __align__(16) unsigned short g_Bl[3 * 131072];
__device__ __align__(16) unsigned short g_Ahi[(size_t)NPAD * 128];  // row-major
__device__ __align__(16) unsigned short g_Alo[(size_t)NPAD * 128];

// ---------------- activations ----------------
__device__ __forceinline__ float softplusf_(float x) {
    return fmaxf(x, 0.f) + __logf(1.f + __expf(-fabsf(x)));
}

// gate for two nodes at once: g2A=(fA,cA), g2B=(fB,cB) in half2.
__device__ __forceinline__ void gate2_(__half2 g2A, __half2 g2B, float& aA, float& aB)
{
    __half2 fAB = __halves2half2(__low2half(g2A), __low2half(g2B));
    __half2 cAB = __halves2half2(__high2half(g2A), __high2half(g2B));
    const __half2 h_half = __float2half2_rn(0.5f);
    __half2 th, u;
    __half2 harg = __hmul2(fAB, h_half);
    asm("tanh.approx.f16x2 %0, %1;" : "=r"(*(unsigned*)&th) : "r"(*(unsigned*)&harg));
    __half2 sig = __hfma2(th, h_half, h_half);
    __half2 relu = __hmax2(cAB, __float2half2_rn(0.f));
    __half2 earg = __hmul2(__habs2(cAB), __float2half2_rn(-1.44269504f));
    asm("ex2.approx.f16x2 %0, %1;" : "=r"(*(unsigned*)&u) : "r"(*(unsigned*)&earg));
    float2 uf = __half22float2(u);
    float2 rf = __half22float2(relu);
    float2 sgf = __half22float2(sig);
    float lx = __logf(1.f + uf.x);
    float ly = __logf(1.f + uf.y);
    aA = fmaf(sgf.x, rf.x + lx, aA);
    aB = fmaf(sgf.y, rf.y + ly, aB);
}

// ---------------- bf16 mma helper ----------------
__device__ __forceinline__ void mma_bf16(float* c, const unsigned* a, unsigned b0, unsigned b1)
{
    asm volatile(
        "mma.sync.aligned.m16n8k16.row.col.f32.bf16.bf16.f32 "
        "{%0,%1,%2,%3},{%4,%5,%6,%7},{%8,%9},{%0,%1,%2,%3};"
        : "+f"(c[0]), "+f"(c[1]), "+f"(c[2]), "+f"(c[3])
        : "r"(a[0]), "r"(a[1]), "r"(a[2]), "r"(a[3]), "r"(b0), "r"(b1));
}

// ---------------- 1: merged prep: detect + folded edge weights + bf16 B planes + embed ----------------
__global__ __launch_bounds__(256) void prep_kernel(
    const unsigned* __restrict__ p2u,
    const float* __restrict__ ae, const float* __restrict__ embW, const float* __restrict__ embB,
    const float* __restrict__ cheFW, const float* __restrict__ cheFb,
    const float* __restrict__ cheGW, const float* __restrict__ cheGb,
    const float* __restrict__ vdwFW, const float* __restrict__ vdwFb,
    const float* __restrict__ vdwGW, const float* __restrict__ vdwGb)
{
    int bid = blockIdx.x;
    int tid = threadIdx.x;
    if (bid == 0 && tid == 0) g_order = (p2u[0] > 1000000u) ? 1 : 0;

    if (bid < 126) {
        int layer = bid / 42, rem = bid % 42;
        int half = rem / 21, k = rem % 21;
        const float* fW = (half ? vdwFW : cheFW) + layer * 2560;
        const float* fb = (half ? vdwFb : cheFb) + layer * 128;
        const float* gW = (half ? vdwGW : cheGW) + (size_t)layer * 98304;
        const float* gb = (half ? vdwGb : cheGb) + layer * 256;
        float* We = g_We + (layer * 2 + half) * 5120;
        float* be = g_be + (layer * 2 + half) * 256;
        int c = tid;
        if (k < ERBF) {
            float s = 0.f;
            for (int hh = 0; hh < 128; hh++) s = fmaf(fW[k * 128 + hh], gW[(size_t)(128 + hh) * 256 + c], s);
            We[k * 256 + c] = s;
        } else {
            float s = gb[c];
            for (int hh = 0; hh < 128; hh++) s = fmaf(fb[hh], gW[(size_t)(128 + hh) * 256 + c], s);
            be[c] = s;
        }
    } else if (bid < 126 + 1536) {
        // bf16 split B planes, n-major [c][k]
        int idx = (bid - 126) * 256 + tid;             // [0, 393216)
        int layer = idx >> 17;
        int within = idx & 131071;
        int k = within >> 10;
        int c = within & 1023;
        int region = c >> 8;                           // 0 S_che, 1 T_che, 2 S_vdw, 3 T_vdw
        int cc = c & 255;
        int h = cc >> 1, p = cc & 1;                   // p=0 filt, p=1 core
        const float* gW = ((region < 2) ? cheGW : vdwGW) + (size_t)layer * 98304;
        int row = ((region & 1) ? 256 : 0) + k;
        float val = gW[(size_t)row * 256 + p * 128 + h];
        __nv_bfloat16 hb = __float2bfloat16(val);
        float hf = __bfloat162float(hb);
        __nv_bfloat16 lb = __float2bfloat16(val - hf);
        size_t o = (size_t)layer * 131072 + (size_t)c * 128 + k;
        g_Bh[o] = *(unsigned short*)&hb;
        g_Bl[o] = *(unsigned short*)&lb;
    } else {
        __shared__ float sW[13 * 128];
        __shared__ float sa[32 * 13];
        int h = tid & 127, grp = tid >> 7;
        int n0 = (bid - (126 + 1536)) * 32;
        for (int i = tid; i < 13 * 128; i += 256) sW[i] = embW[i];
        for (int i = tid; i < 32 * 13; i += 256) sa[i] = ae[n0 * 13 + i];
        float bb = embB[h];
        __syncthreads();
#pragma unroll
        for (int nn = 0; nn < 16; nn++) {
            int ln = grp * 16 + nn;
            float s = bb;
#pragma unroll
            for (int k = 0; k < 13; k++) s = fmaf(sa[ln * 13 + k], sW[k * 128 + h], s);
            g_nodesA[(size_t)(n0 + ln) * 128 + h] = s;
        }
    }
}

// ---------------- 2: edge lookup tables (Chebyshev) -> packed fp16 pairs directly ----------------
__global__ __launch_bounds__(128) void table16_kernel()
{
    int j = blockIdx.x, lh = blockIdx.y, half = lh & 1, h = threadIdx.x;
    const float* We = g_We + lh * 5120;
    float bef = g_be[lh * 256 + h];
    float bec = g_be[lh * 256 + 128 + h];
    float cut  = half ? 12.f : 8.f;
    float dmax = half ? DMAX_VDW : DMAX_CHE;
    float step = dmax / (float)(KNOT - 3);
    int j1 = (j + 1 < KNOT) ? (j + 1) : (KNOT - 1);
    float d0 = (float)j * step, d1 = (float)j1 * step;

    float x0 = d0 * (PI_F / cut), x1 = d1 * (PI_F / cut);
    float sn_0 = sinf(x0), cs_0 = cosf(x0);
    float sn_1 = sinf(x1), cs_1 = cosf(x1);
    float coef0 = (d0 < cut && d0 > 1e-6f) ? 0.5f * (cs_0 + 1.f) / d0 : 0.f;
    float coef1 = (d1 < cut && d1 > 1e-6f) ? 0.5f * (cs_1 + 1.f) / d1 : 0.f;
    float c20 = 2.f * cs_0, c21 = 2.f * cs_1;
    float sk0 = sn_0, skm0 = 0.f, sk1 = sn_1, skm1 = 0.f;
    float f0 = bef, c0 = bec, f1 = bef, c1 = bec;
#pragma unroll
    for (int k = 0; k < ERBF; k++) {
        float wf = We[k * 256 + h], wc = We[k * 256 + 128 + h];
        float r0 = sk0 * coef0, r1 = sk1 * coef1;
        f0 = fmaf(r0, wf, f0); c0 = fmaf(r0, wc, c0);
        f1 = fmaf(r1, wf, f1); c1 = fmaf(r1, wc, c1);
        float t0 = fmaf(c20, sk0, -skm0); skm0 = sk0; sk0 = t0;
        float t1 = fmaf(c21, sk1, -skm1); skm1 = sk1; sk1 = t1;
    }
    __half2 a = __floats2half2_rn(f0, c0);
    __half2 b = __floats2half2_rn(f1, c1);
    uint2 v;
    v.x = *(unsigned*)&a;
    v.y = *(unsigned*)&b;
    g_tab16[((size_t)lh * KNOT + j) * 128 + h] = v;
}

// ---------------- 3: per-layer A split to bf16 hi/lo ----------------
__global__ __launch_bounds__(256) void convA_kernel(int src)
{
    const float* __restrict__ nodes = src ? g_nodesB : g_nodesA;
    int gid = blockIdx.x * 256 + threadIdx.x;   // 20096*16 threads
    int row = gid >> 4, seg = gid & 15;         // 8 elems per thread
    float v[8];
    if (row < NPTS) {
        float4 v0 = *(const float4*)(nodes + (size_t)row * 128 + seg * 8);
        float4 v1 = *(const float4*)(nodes + (size_t)row * 128 + seg * 8 + 4);
        v[0] = v0.x; v[1] = v0.y; v[2] = v0.z; v[3] = v0.w;
        v[4] = v1.x; v[5] = v1.y; v[6] = v1.z; v[7] = v1.w;
    } else {
#pragma unroll
        for (int i = 0; i < 8; i++) v[i] = 0.f;
    }
    unsigned short hs[8], ls[8];
#pragma unroll
    for (int i = 0; i < 8; i++) {
        __nv_bfloat16 hb = __float2bfloat16(v[i]);
        float hf = __bfloat162float(hb);
        __nv_bfloat16 lb = __float2bfloat16(v[i] - hf);
        hs[i] = *(unsigned short*)&hb;
        ls[i] = *(unsigned short*)&lb;
    }
    size_t o = (size_t)row * 128 + seg * 8;
    *(uint4*)(g_Ahi + o) = *(uint4*)hs;
    *(uint4*)(g_Alo + o) = *(uint4*)ls;
}

// ---------------- 4: tensor-core ST GEMM (bf16 3-term split), fp16 epilogue ----------------
// grid (157, 8), 256 threads, dyn smem 73728 B
__global__ __launch_bounds__(256, 2) void mma_kernel(int layer)
{
    extern __shared__ __align__(16) unsigned short smu[];
    unsigned short* sAh = smu;                 // 128 rows x 72 (pitch 144B)
    unsigned short* sAl = sAh + 128 * 72;
    unsigned short* sBh = sAl + 128 * 72;
    unsigned short* sBl = sBh + 128 * 72;

    int tid = threadIdx.x;
    int lane = tid & 31, wid = tid >> 5;
    int g = lane >> 2, tg = lane & 3;
    int wm = wid & 3, wn = wid >> 2;
    int r0 = blockIdx.x * 128;
    int c0 = blockIdx.y * 128;

    const unsigned short* gA_h = g_Ahi + (size_t)r0 * 128;
    const unsigned short* gA_l = g_Alo + (size_t)r0 * 128;
    const unsigned short* gB_h = g_Bh + (size_t)layer * 131072 + (size_t)c0 * 128;
    const unsigned short* gB_l = g_Bl + (size_t)layer * 131072 + (size_t)c0 * 128;

    float acc[2][8][4];
#pragma unroll
    for (int a = 0; a < 2; a++)
#pragma unroll
        for (int b = 0; b < 8; b++)
#pragma unroll
            for (int c = 0; c < 4; c++) acc[a][b][c] = 0.f;

#pragma unroll 1
    for (int kc = 0; kc < 2; kc++) {
        __syncthreads();
#pragma unroll
        for (int it = 0; it < 4; it++) {
            int i = tid + it * 256;            // 0..1023
            int row = i >> 3, pos = i & 7;
            int goff = row * 128 + kc * 64 + pos * 8;
            int soff = row * 72 + pos * 8;
            *(uint4*)(sAh + soff) = *(const uint4*)(gA_h + goff);
            *(uint4*)(sAl + soff) = *(const uint4*)(gA_l + goff);
            *(uint4*)(sBh + soff) = *(const uint4*)(gB_h + goff);
            *(uint4*)(sBl + soff) = *(const uint4*)(gB_l + goff);
        }
        __syncthreads();

#pragma unroll
        for (int ks = 0; ks < 4; ks++) {
            unsigned ah[2][4], al[2][4];
#pragma unroll
            for (int mt = 0; mt < 2; mt++) {
                int base = (wm * 32 + mt * 16 + g) * 72 + ks * 16 + tg * 2;
                ah[mt][0] = *(const unsigned*)(sAh + base);
                ah[mt][1] = *(const unsigned*)(sAh + base + 8 * 72);
                ah[mt][2] = *(const unsigned*)(sAh + base + 8);
                ah[mt][3] = *(const unsigned*)(sAh + base + 8 * 72 + 8);
                al[mt][0] = *(const unsigned*)(sAl + base);
                al[mt][1] = *(const unsigned*)(sAl + base + 8 * 72);
                al[mt][2] = *(const unsigned*)(sAl + base + 8);
                al[mt][3] = *(const unsigned*)(sAl + base + 8 * 72 + 8);
            }
#pragma unroll
            for (int nt = 0; nt < 8; nt++) {
                int nb = (wn * 64 + nt * 8 + g) * 72 + ks * 16 + tg * 2;
                unsigned b0h = *(const unsigned*)(sBh + nb);
                unsigned b1h = *(const unsigned*)(sBh + nb + 8);
                unsigned b0l = *(const unsigned*)(sBl + nb);
                unsigned b1l = *(const unsigned*)(sBl + nb + 8);
#pragma unroll
                for (int mt = 0; mt < 2; mt++) {
                    mma_bf16(acc[mt][nt], ah[mt], b0h, b1h);
                    mma_bf16(acc[mt][nt], al[mt], b0h, b1h);
                    mma_bf16(acc[mt][nt], ah[mt], b0l, b1l);
                }
            }
        }
    }

    // epilogue: fp16 pairs straight into g_STh
#pragma unroll
    for (int mt = 0; mt < 2; mt++) {
        int m = r0 + wm * 32 + mt * 16 + g;
#pragma unroll
        for (int nt = 0; nt < 8; nt++) {
            int col = c0 + wn * 64 + nt * 8 + tg * 2;
            __half2 v0 = __floats2half2_rn(acc[mt][nt][0], acc[mt][nt][1]);
            __half2 v1 = __floats2half2_rn(acc[mt][nt][2], acc[mt][nt][3]);
            if (m < NPTS)     g_STh[(size_t)m * 512 + (col >> 1)] = v0;
            if (m + 8 < NPTS) g_STh[(size_t)(m + 8) * 512 + (col >> 1)] = v1;
        }
    }
}

// ---------------- 5: fused gated conv — full unroll, f16x2 gate, 2-node pipelines ----------------
__global__ __launch_bounds__(128) void conv_kernel(
    const float* __restrict__ che_fea, const float* __restrict__ p2f, const float* __restrict__ p3f,
    const int* __restrict__ p2i, const int* __restrict__ p3i,
    const int* __restrict__ vdw_idx, int src, int layer)
{
    const int* che_idx = g_order ? p3i : p2i;
    const float* vdw_fea = g_order ? p2f : p3f;
    const float* __restrict__ nodes = src ? g_nodesB : g_nodesA;
    float* __restrict__ nodes_out = src ? g_nodesA : g_nodesB;

    __shared__ __align__(16) uint4 s_pk[NBLK * MNBR];   // {idx_byteoff, knot_byteoff, fr_half2, 0}
    __shared__ float s_acc[NBLK * 128];

    int h = threadIdx.x;
    int n0 = blockIdx.x * NBLK;
#pragma unroll
    for (int i = 0; i < NBLK; i++) s_acc[i * 128 + h] = 0.f;

#pragma unroll 1
    for (int half = 0; half < 2; half++) {
        const char* tbb = (const char*)(g_tab16 + (size_t)(layer * 2 + half) * KNOT * 128) + h * 8;
        const float* feap = half ? vdw_fea : che_fea;
        const int* idxp = half ? vdw_idx : che_idx;
        float scale = half ? ((float)(KNOT - 3) / DMAX_VDW) : ((float)(KNOT - 3) / DMAX_CHE);
        const char* stb = (const char*)g_STh + ((half ? 384 : 128) + h) * 4;  // T region byte base
        int soff = (half ? 256 : 0) + h;                                       // S region half2 index

        __syncthreads();
        for (int i = h; i < NBLK * MNBR; i += 128) {
            float d = feap[n0 * MNBR + i];
            float u = fminf(d * scale, (float)(KNOT - 3));
            float jf = floorf(u);
            float fr = u - jf;
            __half2 frh = __float2half2_rn(fr);
            s_pk[i] = make_uint4((unsigned)idxp[n0 * MNBR + i] * 2048u,
                                 (unsigned)jf * 1024u,
                                 *(unsigned*)&frh, 0u);
        }
        __syncthreads();

#pragma unroll 1
        for (int nn = 0; nn < NBLK; nn += 2) {
            int nA = n0 + nn, nB = nA + 1;
            int iA = nn * MNBR, iB = iA + MNBR;
            __half2 svA = g_STh[(size_t)nA * 512 + soff];
            __half2 svB = g_STh[(size_t)nB * 512 + soff];

            __half2 tgA[2], tgB[2];
            uint2   tpA[2], tpB[2];
            unsigned frA[2], frB[2];
#pragma unroll
            for (int s = 0; s < 2; s++) {
                uint4 pA = s_pk[iA + s];
                uint4 pB = s_pk[iB + s];
                tgA[s] = *(const __half2*)(stb + pA.x);
                tpA[s] = *(const uint2*)(tbb + pA.y);
                frA[s] = pA.z;
                tgB[s] = *(const __half2*)(stb + pB.x);
                tpB[s] = *(const uint2*)(tbb + pB.y);
                frB[s] = pB.z;
            }

            float aA = 0.f, aB = 0.f;
#pragma unroll
            for (int m = 0; m < MNBR; m++) {
                int s = m & 1;
                __half2 tgAc = tgA[s]; uint2 tpAc = tpA[s]; unsigned frAc = frA[s];
                __half2 tgBc = tgB[s]; uint2 tpBc = tpB[s]; unsigned frBc = frB[s];
                if (m + 2 < MNBR) {
                    uint4 pA = s_pk[iA + m + 2];
                    uint4 pB = s_pk[iB + m + 2];
                    tgA[s] = *(const __half2*)(stb + pA.x);
                    tpA[s] = *(const uint2*)(tbb + pA.y);
                    frA[s] = pA.z;
                    tgB[s] = *(const __half2*)(stb + pB.x);
                    tpB[s] = *(const uint2*)(tbb + pB.y);
                    frB[s] = pB.z;
                }

                __half2 t0A = *(__half2*)&tpAc.x, t1A = *(__half2*)&tpAc.y;
                __half2 eA = __hfma2(*(__half2*)&frAc, __hsub2(t1A, t0A), t0A);
                __half2 g2A = __hadd2(__hadd2(svA, tgAc), eA);
                __half2 t0B = *(__half2*)&tpBc.x, t1B = *(__half2*)&tpBc.y;
                __half2 eB = __hfma2(*(__half2*)&frBc, __hsub2(t1B, t0B), t0B);
                __half2 g2B = __hadd2(__hadd2(svB, tgBc), eB);
                gate2_(g2A, g2B, aA, aB);
            }
            s_acc[nn * 128 + h]       += aA;
            s_acc[(nn + 1) * 128 + h] += aB;
        }
    }
#pragma unroll
    for (int nn = 0; nn < NBLK; nn++) {
        int n = n0 + nn;
        float r = nodes[(size_t)n * 128 + h] + s_acc[nn * 128 + h];
        nodes_out[(size_t)n * 128 + h] = softplusf_(r);
    }
}

// ---------------- 6: pooling + MLP head ----------------
__global__ __launch_bounds__(128) void pool_kernel(
    const int* __restrict__ num_atoms,
    const float* __restrict__ fc1W, const float* __restrict__ fc1b,
    const float* __restrict__ outW, const float* __restrict__ outb,
    float* __restrict__ out, int src)
{
    const float* __restrict__ nodes = src ? g_nodesB : g_nodesA;
    __shared__ float sA[128];
    __shared__ float sB[128];
    __shared__ int sred[128];
    int b = blockIdx.x, h = threadIdx.x;

    int v = 0;
    for (int i = h; i < b; i += 128) v += num_atoms[i];
    sred[h] = v;
    __syncthreads();
    for (int off = 64; off > 0; off >>= 1) {
        if (h < off) sred[h] += sred[h + off];
        __syncthreads();
    }
    int start = sred[0];
    int cnt = num_atoms[b];

    float s = 0.f;
    for (int a = 0; a < cnt; a++) s += nodes[(size_t)(start + a) * 128 + h];
    sA[h] = softplusf_(s / (float)cnt);
    __syncthreads();
    float t = fc1b[h];
    for (int k = 0; k < 128; k++) t = fmaf(sA[k], fc1W[k * 128 + h], t);
    sB[h] = softplusf_(t) * outW[h];
    __syncthreads();
    for (int off = 64; off > 0; off >>= 1) {
        if (h < off) sB[h] += sB[h + off];
        __syncthreads();
    }
    if (h == 0) out[b] = sB[0] + outb[0];
}

// ---------------- launch ----------------
extern "C" void kernel_launch(void* const* d_in, const int* in_sizes, int n_in,
                              void* d_out, int out_size)
{
    const float* ae      = (const float*)d_in[0];
    const float* che_fea = (const float*)d_in[1];
    const void*  p2      = d_in[2];
    const void*  p3      = d_in[3];
    const int*   vdw_idx = (const int*)d_in[4];
    const int*   natoms  = (const int*)d_in[5];
    const float* embW    = (const float*)d_in[6];
    const float* embB    = (const float*)d_in[7];
    const float* cheFW   = (const float*)d_in[8];
    const float* cheFb   = (const float*)d_in[9];
    const float* cheGW   = (const float*)d_in[10];
    const float* cheGb   = (const float*)d_in[11];
    const float* vdwFW   = (const float*)d_in[12];
    const float* vdwFb   = (const float*)d_in[13];
    const float* vdwGW   = (const float*)d_in[14];
    const float* vdwGb   = (const float*)d_in[15];
    const float* fc1W    = (const float*)d_in[16];
    const float* fc1b    = (const float*)d_in[17];
    const float* outW    = (const float*)d_in[18];
    const float* outb    = (const float*)d_in[19];

    const int MMA_SMEM = 4 * 128 * 72 * 2;   // 73728 B
    static int attr_set = 0;
    if (!attr_set) {
        cudaFuncSetAttribute(mma_kernel, cudaFuncAttributeMaxDynamicSharedMemorySize, MMA_SMEM);
        attr_set = 1;
    }

    prep_kernel<<<126 + 1536 + 625, 256>>>((const unsigned*)p2, ae, embW, embB,
                                           cheFW, cheFb, cheGW, cheGb,
                                           vdwFW, vdwFb, vdwGW, vdwGb);
    table16_kernel<<<dim3(KNOT, 6), 128>>>();

    int src = 0;
    for (int i = 0; i < 3; i++) {
        convA_kernel<<<NPAD * 16 / 256, 256>>>(src);
        mma_kernel<<<dim3(157, 8), 256, MMA_SMEM>>>(i);
        conv_kernel<<<NPTS / NBLK, 128>>>(che_fea, (const float*)p2, (const float*)p3,
                                          (const int*)p2, (const int*)p3, vdw_idx, src, i);
        src ^= 1;
    }
    pool_kernel<<<BCRY, 128>>>(natoms, fc1W, fc1b, outW, outb, (float*)d_out, src);
}

// round 12
// speedup vs baseline: 2.1010x; 1.0308x over previous
#include <cuda_runtime.h>
#include <cuda_fp16.h>
#include <cuda_bf16.h>
#include <cstdint>

// ---------------- problem constants ----------------
#define NPTS 20000
#define NPAD 20096          // 157*128
#define MNBR 20
#define ERBF 20
#define HDIM 128
#define BCRY 200
#define NBLK 8
#define PI_F 3.14159265358979f
#define KNOT 4096
#define DMAX_CHE 8.81f
#define DMAX_VDW 13.21f

typedef unsigned long long u64;

// ---------------- device scratch ----------------
__device__ int   g_order;
__device__ float g_nodesA[NPTS * HDIM];
__device__ float g_nodesB[NPTS * HDIM];
__device__ __half2 g_STh[(size_t)NPTS * 512];            // [S_che|T_che|S_vdw|T_vdw] x 128 half2 (filt,core)
__device__ float g_We[3 * 2 * ERBF * 256];
__device__ float g_be[3 * 2 * 256];
__device__ uint2 g_tab16[(size_t)3 * 2 * KNOT * 128];    // packed fp16: {f_j,c_j,f_j+1,c_j+1} per (j,h)
// bf16 split operands for tensor-core GEMM (tail rows stay zero from static init)
__device__ __align__(16) unsigned short g_Bh[3 * 131072];   // [layer][c(1024)][k(128)] n-major
__device__ __align__(16) unsigned short g_Bl[3 * 131072];
__device__ __align__(16) unsigned short g_Ahi[(size_t)NPAD * 128];  // row-major
__device__ __align__(16) unsigned short g_Alo[(size_t)NPAD * 128];

// ---------------- activations ----------------
__device__ __forceinline__ float softplusf_(float x) {
    return fmaxf(x, 0.f) + __logf(1.f + __expf(-fabsf(x)));
}

// gate for two nodes at once: g2A=(fA,cA), g2B=(fB,cB) in half2.
__device__ __forceinline__ void gate2_(__half2 g2A, __half2 g2B, float& aA, float& aB)
{
    __half2 fAB = __halves2half2(__low2half(g2A), __low2half(g2B));
    __half2 cAB = __halves2half2(__high2half(g2A), __high2half(g2B));
    const __half2 h_half = __float2half2_rn(0.5f);
    __half2 th, u;
    __half2 harg = __hmul2(fAB, h_half);
    asm("tanh.approx.f16x2 %0, %1;" : "=r"(*(unsigned*)&th) : "r"(*(unsigned*)&harg));
    __half2 sig = __hfma2(th, h_half, h_half);
    __half2 relu = __hmax2(cAB, __float2half2_rn(0.f));
    __half2 earg = __hmul2(__habs2(cAB), __float2half2_rn(-1.44269504f));
    asm("ex2.approx.f16x2 %0, %1;" : "=r"(*(unsigned*)&u) : "r"(*(unsigned*)&earg));
    float2 uf = __half22float2(u);
    float2 rf = __half22float2(relu);
    float2 sgf = __half22float2(sig);
    float lx = __logf(1.f + uf.x);
    float ly = __logf(1.f + uf.y);
    aA = fmaf(sgf.x, rf.x + lx, aA);
    aB = fmaf(sgf.y, rf.y + ly, aB);
}

// ---------------- bf16 split helper ----------------
__device__ __forceinline__ void bf16split(float v, unsigned short& hs, unsigned short& ls)
{
    __nv_bfloat16 hb = __float2bfloat16(v);
    float hf = __bfloat162float(hb);
    __nv_bfloat16 lb = __float2bfloat16(v - hf);
    hs = *(unsigned short*)&hb;
    ls = *(unsigned short*)&lb;
}

// ---------------- bf16 mma / ldmatrix helpers ----------------
__device__ __forceinline__ void mma_bf16(float* c, const unsigned* a, unsigned b0, unsigned b1)
{
    asm volatile(
        "mma.sync.aligned.m16n8k16.row.col.f32.bf16.bf16.f32 "
        "{%0,%1,%2,%3},{%4,%5,%6,%7},{%8,%9},{%0,%1,%2,%3};"
        : "+f"(c[0]), "+f"(c[1]), "+f"(c[2]), "+f"(c[3])
        : "r"(a[0]), "r"(a[1]), "r"(a[2]), "r"(a[3]), "r"(b0), "r"(b1));
}
__device__ __forceinline__ void ldsm_x4(unsigned* r, const unsigned short* p)
{
    unsigned addr = (unsigned)__cvta_generic_to_shared(p);
    asm volatile("ldmatrix.sync.aligned.m8n8.x4.shared.b16 {%0,%1,%2,%3}, [%4];"
                 : "=r"(r[0]), "=r"(r[1]), "=r"(r[2]), "=r"(r[3]) : "r"(addr));
}

// ---------------- 1: merged prep: detect + folded edge weights + bf16 B planes + embed(+split) ----------------
__global__ __launch_bounds__(256) void prep_kernel(
    const unsigned* __restrict__ p2u,
    const float* __restrict__ ae, const float* __restrict__ embW, const float* __restrict__ embB,
    const float* __restrict__ cheFW, const float* __restrict__ cheFb,
    const float* __restrict__ cheGW, const float* __restrict__ cheGb,
    const float* __restrict__ vdwFW, const float* __restrict__ vdwFb,
    const float* __restrict__ vdwGW, const float* __restrict__ vdwGb)
{
    int bid = blockIdx.x;
    int tid = threadIdx.x;
    if (bid == 0 && tid == 0) g_order = (p2u[0] > 1000000u) ? 1 : 0;

    if (bid < 126) {
        int layer = bid / 42, rem = bid % 42;
        int half = rem / 21, k = rem % 21;
        const float* fW = (half ? vdwFW : cheFW) + layer * 2560;
        const float* fb = (half ? vdwFb : cheFb) + layer * 128;
        const float* gW = (half ? vdwGW : cheGW) + (size_t)layer * 98304;
        const float* gb = (half ? vdwGb : cheGb) + layer * 256;
        float* We = g_We + (layer * 2 + half) * 5120;
        float* be = g_be + (layer * 2 + half) * 256;
        int c = tid;
        if (k < ERBF) {
            float s = 0.f;
            for (int hh = 0; hh < 128; hh++) s = fmaf(fW[k * 128 + hh], gW[(size_t)(128 + hh) * 256 + c], s);
            We[k * 256 + c] = s;
        } else {
            float s = gb[c];
            for (int hh = 0; hh < 128; hh++) s = fmaf(fb[hh], gW[(size_t)(128 + hh) * 256 + c], s);
            be[c] = s;
        }
    } else if (bid < 126 + 1536) {
        // bf16 split B planes, n-major [c][k]
        int idx = (bid - 126) * 256 + tid;             // [0, 393216)
        int layer = idx >> 17;
        int within = idx & 131071;
        int k = within >> 10;
        int c = within & 1023;
        int region = c >> 8;                           // 0 S_che, 1 T_che, 2 S_vdw, 3 T_vdw
        int cc = c & 255;
        int h = cc >> 1, p = cc & 1;                   // p=0 filt, p=1 core
        const float* gW = ((region < 2) ? cheGW : vdwGW) + (size_t)layer * 98304;
        int row = ((region & 1) ? 256 : 0) + k;
        float val = gW[(size_t)row * 256 + p * 128 + h];
        size_t o = (size_t)layer * 131072 + (size_t)c * 128 + k;
        bf16split(val, g_Bh[o], g_Bl[o]);
    } else {
        __shared__ float sW[13 * 128];
        __shared__ float sa[32 * 13];
        int h = tid & 127, grp = tid >> 7;
        int n0 = (bid - (126 + 1536)) * 32;
        for (int i = tid; i < 13 * 128; i += 256) sW[i] = embW[i];
        for (int i = tid; i < 32 * 13; i += 256) sa[i] = ae[n0 * 13 + i];
        float bb = embB[h];
        __syncthreads();
#pragma unroll
        for (int nn = 0; nn < 16; nn++) {
            int ln = grp * 16 + nn;
            float s = bb;
#pragma unroll
            for (int k = 0; k < 13; k++) s = fmaf(sa[ln * 13 + k], sW[k * 128 + h], s);
            int n = n0 + ln;
            g_nodesA[(size_t)n * 128 + h] = s;
            bf16split(s, g_Ahi[(size_t)n * 128 + h], g_Alo[(size_t)n * 128 + h]);
        }
    }
}

// ---------------- 2: edge lookup tables (Chebyshev) -> packed fp16 pairs directly ----------------
__global__ __launch_bounds__(128) void table16_kernel()
{
    int j = blockIdx.x, lh = blockIdx.y, half = lh & 1, h = threadIdx.x;
    const float* We = g_We + lh * 5120;
    float bef = g_be[lh * 256 + h];
    float bec = g_be[lh * 256 + 128 + h];
    float cut  = half ? 12.f : 8.f;
    float dmax = half ? DMAX_VDW : DMAX_CHE;
    float step = dmax / (float)(KNOT - 3);
    int j1 = (j + 1 < KNOT) ? (j + 1) : (KNOT - 1);
    float d0 = (float)j * step, d1 = (float)j1 * step;

    float x0 = d0 * (PI_F / cut), x1 = d1 * (PI_F / cut);
    float sn_0 = sinf(x0), cs_0 = cosf(x0);
    float sn_1 = sinf(x1), cs_1 = cosf(x1);
    float coef0 = (d0 < cut && d0 > 1e-6f) ? 0.5f * (cs_0 + 1.f) / d0 : 0.f;
    float coef1 = (d1 < cut && d1 > 1e-6f) ? 0.5f * (cs_1 + 1.f) / d1 : 0.f;
    float c20 = 2.f * cs_0, c21 = 2.f * cs_1;
    float sk0 = sn_0, skm0 = 0.f, sk1 = sn_1, skm1 = 0.f;
    float f0 = bef, c0 = bec, f1 = bef, c1 = bec;
#pragma unroll
    for (int k = 0; k < ERBF; k++) {
        float wf = We[k * 256 + h], wc = We[k * 256 + 128 + h];
        float r0 = sk0 * coef0, r1 = sk1 * coef1;
        f0 = fmaf(r0, wf, f0); c0 = fmaf(r0, wc, c0);
        f1 = fmaf(r1, wf, f1); c1 = fmaf(r1, wc, c1);
        float t0 = fmaf(c20, sk0, -skm0); skm0 = sk0; sk0 = t0;
        float t1 = fmaf(c21, sk1, -skm1); skm1 = sk1; sk1 = t1;
    }
    __half2 a = __floats2half2_rn(f0, c0);
    __half2 b = __floats2half2_rn(f1, c1);
    uint2 v;
    v.x = *(unsigned*)&a;
    v.y = *(unsigned*)&b;
    g_tab16[((size_t)lh * KNOT + j) * 128 + h] = v;
}

// ---------------- 3: tensor-core ST GEMM (bf16 3-term split), ldmatrix fragments ----------------
// grid (157, 8), 256 threads, dyn smem 73728 B
__global__ __launch_bounds__(256, 2) void mma_kernel(int layer)
{
    extern __shared__ __align__(16) unsigned short smu[];
    unsigned short* sAh = smu;                 // 128 rows x 72 (pitch 144B)
    unsigned short* sAl = sAh + 128 * 72;
    unsigned short* sBh = sAl + 128 * 72;
    unsigned short* sBl = sBh + 128 * 72;

    int tid = threadIdx.x;
    int lane = tid & 31, wid = tid >> 5;
    int g = lane >> 2, tg = lane & 3;
    int wm = wid & 3, wn = wid >> 2;
    int r0 = blockIdx.x * 128;
    int c0 = blockIdx.y * 128;

    // ldmatrix lane address components
    int mrow = lane & 7, msel = lane >> 3;
    int a_row = (msel & 1) * 8 + mrow;         // row within 16-row tile
    int a_col = (msel >> 1) * 8;               // k offset within 16
    int b_row = (msel >> 1) * 8 + mrow;        // n within 16 (covers 2 n-tiles)
    int b_col = (msel & 1) * 8;                // k offset within 16

    const unsigned short* gA_h = g_Ahi + (size_t)r0 * 128;
    const unsigned short* gA_l = g_Alo + (size_t)r0 * 128;
    const unsigned short* gB_h = g_Bh + (size_t)layer * 131072 + (size_t)c0 * 128;
    const unsigned short* gB_l = g_Bl + (size_t)layer * 131072 + (size_t)c0 * 128;

    float acc[2][8][4];
#pragma unroll
    for (int a = 0; a < 2; a++)
#pragma unroll
        for (int b = 0; b < 8; b++)
#pragma unroll
            for (int c = 0; c < 4; c++) acc[a][b][c] = 0.f;

#pragma unroll 1
    for (int kc = 0; kc < 2; kc++) {
        __syncthreads();
#pragma unroll
        for (int it = 0; it < 4; it++) {
            int i = tid + it * 256;            // 0..1023
            int row = i >> 3, pos = i & 7;
            int goff = row * 128 + kc * 64 + pos * 8;
            int soff = row * 72 + pos * 8;
            *(uint4*)(sAh + soff) = *(const uint4*)(gA_h + goff);
            *(uint4*)(sAl + soff) = *(const uint4*)(gA_l + goff);
            *(uint4*)(sBh + soff) = *(const uint4*)(gB_h + goff);
            *(uint4*)(sBl + soff) = *(const uint4*)(gB_l + goff);
        }
        __syncthreads();

#pragma unroll
        for (int ks = 0; ks < 4; ks++) {
            unsigned ah[2][4], al[2][4];
#pragma unroll
            for (int mt = 0; mt < 2; mt++) {
                int off = (wm * 32 + mt * 16 + a_row) * 72 + ks * 16 + a_col;
                ldsm_x4(ah[mt], sAh + off);
                ldsm_x4(al[mt], sAl + off);
            }
#pragma unroll
            for (int nt2 = 0; nt2 < 4; nt2++) {
                int off = (wn * 64 + nt2 * 16 + b_row) * 72 + ks * 16 + b_col;
                unsigned bh4[4], bl4[4];
                ldsm_x4(bh4, sBh + off);
                ldsm_x4(bl4, sBl + off);
#pragma unroll
                for (int half = 0; half < 2; half++) {
                    int nt = nt2 * 2 + half;
                    unsigned b0h = bh4[half * 2], b1h = bh4[half * 2 + 1];
                    unsigned b0l = bl4[half * 2], b1l = bl4[half * 2 + 1];
#pragma unroll
                    for (int mt = 0; mt < 2; mt++) {
                        mma_bf16(acc[mt][nt], ah[mt], b0h, b1h);
                        mma_bf16(acc[mt][nt], al[mt], b0h, b1h);
                        mma_bf16(acc[mt][nt], ah[mt], b0l, b1l);
                    }
                }
            }
        }
    }

    // epilogue: fp16 pairs straight into g_STh
#pragma unroll
    for (int mt = 0; mt < 2; mt++) {
        int m = r0 + wm * 32 + mt * 16 + g;
#pragma unroll
        for (int nt = 0; nt < 8; nt++) {
            int col = c0 + wn * 64 + nt * 8 + tg * 2;
            __half2 v0 = __floats2half2_rn(acc[mt][nt][0], acc[mt][nt][1]);
            __half2 v1 = __floats2half2_rn(acc[mt][nt][2], acc[mt][nt][3]);
            if (m < NPTS)     g_STh[(size_t)m * 512 + (col >> 1)] = v0;
            if (m + 8 < NPTS) g_STh[(size_t)(m + 8) * 512 + (col >> 1)] = v1;
        }
    }
}

// ---------------- 4: fused gated conv — full unroll, f16x2 gate, 2-node pipelines, fused split ----------------
__global__ __launch_bounds__(128) void conv_kernel(
    const float* __restrict__ che_fea, const float* __restrict__ p2f, const float* __restrict__ p3f,
    const int* __restrict__ p2i, const int* __restrict__ p3i,
    const int* __restrict__ vdw_idx, int src, int layer)
{
    const int* che_idx = g_order ? p3i : p2i;
    const float* vdw_fea = g_order ? p2f : p3f;
    const float* __restrict__ nodes = src ? g_nodesB : g_nodesA;
    float* __restrict__ nodes_out = src ? g_nodesA : g_nodesB;

    __shared__ __align__(16) uint4 s_pk[NBLK * MNBR];   // {idx_byteoff, knot_byteoff, fr_half2, 0}
    __shared__ float s_acc[NBLK * 128];

    int h = threadIdx.x;
    int n0 = blockIdx.x * NBLK;
#pragma unroll
    for (int i = 0; i < NBLK; i++) s_acc[i * 128 + h] = 0.f;

#pragma unroll 1
    for (int half = 0; half < 2; half++) {
        const char* tbb = (const char*)(g_tab16 + (size_t)(layer * 2 + half) * KNOT * 128) + h * 8;
        const float* feap = half ? vdw_fea : che_fea;
        const int* idxp = half ? vdw_idx : che_idx;
        float scale = half ? ((float)(KNOT - 3) / DMAX_VDW) : ((float)(KNOT - 3) / DMAX_CHE);
        const char* stb = (const char*)g_STh + ((half ? 384 : 128) + h) * 4;  // T region byte base
        int soff = (half ? 256 : 0) + h;                                       // S region half2 index

        __syncthreads();
        for (int i = h; i < NBLK * MNBR; i += 128) {
            float d = feap[n0 * MNBR + i];
            float u = fminf(d * scale, (float)(KNOT - 3));
            float jf = floorf(u);
            float fr = u - jf;
            __half2 frh = __float2half2_rn(fr);
            s_pk[i] = make_uint4((unsigned)idxp[n0 * MNBR + i] * 2048u,
                                 (unsigned)jf * 1024u,
                                 *(unsigned*)&frh, 0u);
        }
        __syncthreads();

#pragma unroll 1
        for (int nn = 0; nn < NBLK; nn += 2) {
            int nA = n0 + nn, nB = nA + 1;
            int iA = nn * MNBR, iB = iA + MNBR;
            __half2 svA = g_STh[(size_t)nA * 512 + soff];
            __half2 svB = g_STh[(size_t)nB * 512 + soff];

            __half2 tgA[2], tgB[2];
            uint2   tpA[2], tpB[2];
            unsigned frA[2], frB[2];
#pragma unroll
            for (int s = 0; s < 2; s++) {
                uint4 pA = s_pk[iA + s];
                uint4 pB = s_pk[iB + s];
                tgA[s] = *(const __half2*)(stb + pA.x);
                tpA[s] = *(const uint2*)(tbb + pA.y);
                frA[s] = pA.z;
                tgB[s] = *(const __half2*)(stb + pB.x);
                tpB[s] = *(const uint2*)(tbb + pB.y);
                frB[s] = pB.z;
            }

            float aA = 0.f, aB = 0.f;
#pragma unroll
            for (int m = 0; m < MNBR; m++) {
                int s = m & 1;
                __half2 tgAc = tgA[s]; uint2 tpAc = tpA[s]; unsigned frAc = frA[s];
                __half2 tgBc = tgB[s]; uint2 tpBc = tpB[s]; unsigned frBc = frB[s];
                if (m + 2 < MNBR) {
                    uint4 pA = s_pk[iA + m + 2];
                    uint4 pB = s_pk[iB + m + 2];
                    tgA[s] = *(const __half2*)(stb + pA.x);
                    tpA[s] = *(const uint2*)(tbb + pA.y);
                    frA[s] = pA.z;
                    tgB[s] = *(const __half2*)(stb + pB.x);
                    tpB[s] = *(const uint2*)(tbb + pB.y);
                    frB[s] = pB.z;
                }

                __half2 t0A = *(__half2*)&tpAc.x, t1A = *(__half2*)&tpAc.y;
                __half2 eA = __hfma2(*(__half2*)&frAc, __hsub2(t1A, t0A), t0A);
                __half2 g2A = __hadd2(__hadd2(svA, tgAc), eA);
                __half2 t0B = *(__half2*)&tpBc.x, t1B = *(__half2*)&tpBc.y;
                __half2 eB = __hfma2(*(__half2*)&frBc, __hsub2(t1B, t0B), t0B);
                __half2 g2B = __hadd2(__hadd2(svB, tgBc), eB);
                gate2_(g2A, g2B, aA, aB);
            }
            s_acc[nn * 128 + h]       += aA;
            s_acc[(nn + 1) * 128 + h] += aB;
        }
    }
#pragma unroll
    for (int nn = 0; nn < NBLK; nn++) {
        int n = n0 + nn;
        float r = nodes[(size_t)n * 128 + h] + s_acc[nn * 128 + h];
        float sp = softplusf_(r);
        nodes_out[(size_t)n * 128 + h] = sp;
        bf16split(sp, g_Ahi[(size_t)n * 128 + h], g_Alo[(size_t)n * 128 + h]);
    }
}

// ---------------- 5: pooling + MLP head ----------------
__global__ __launch_bounds__(128) void pool_kernel(
    const int* __restrict__ num_atoms,
    const float* __restrict__ fc1W, const float* __restrict__ fc1b,
    const float* __restrict__ outW, const float* __restrict__ outb,
    float* __restrict__ out, int src)
{
    const float* __restrict__ nodes = src ? g_nodesB : g_nodesA;
    __shared__ float sA[128];
    __shared__ float sB[128];
    __shared__ int sred[128];
    int b = blockIdx.x, h = threadIdx.x;

    int v = 0;
    for (int i = h; i < b; i += 128) v += num_atoms[i];
    sred[h] = v;
    __syncthreads();
    for (int off = 64; off > 0; off >>= 1) {
        if (h < off) sred[h] += sred[h + off];
        __syncthreads();
    }
    int start = sred[0];
    int cnt = num_atoms[b];

    float s = 0.f;
    for (int a = 0; a < cnt; a++) s += nodes[(size_t)(start + a) * 128 + h];
    sA[h] = softplusf_(s / (float)cnt);
    __syncthreads();
    float t = fc1b[h];
    for (int k = 0; k < 128; k++) t = fmaf(sA[k], fc1W[k * 128 + h], t);
    sB[h] = softplusf_(t) * outW[h];
    __syncthreads();
    for (int off = 64; off > 0; off >>= 1) {
        if (h < off) sB[h] += sB[h + off];
        __syncthreads();
    }
    if (h == 0) out[b] = sB[0] + outb[0];
}

// ---------------- launch ----------------
extern "C" void kernel_launch(void* const* d_in, const int* in_sizes, int n_in,
                              void* d_out, int out_size)
{
    const float* ae      = (const float*)d_in[0];
    const float* che_fea = (const float*)d_in[1];
    const void*  p2      = d_in[2];
    const void*  p3      = d_in[3];
    const int*   vdw_idx = (const int*)d_in[4];
    const int*   natoms  = (const int*)d_in[5];
    const float* embW    = (const float*)d_in[6];
    const float* embB    = (const float*)d_in[7];
    const float* cheFW   = (const float*)d_in[8];
    const float* cheFb   = (const float*)d_in[9];
    const float* cheGW   = (const float*)d_in[10];
    const float* cheGb   = (const float*)d_in[11];
    const float* vdwFW   = (const float*)d_in[12];
    const float* vdwFb   = (const float*)d_in[13];
    const float* vdwGW   = (const float*)d_in[14];
    const float* vdwGb   = (const float*)d_in[15];
    const float* fc1W    = (const float*)d_in[16];
    const float* fc1b    = (const float*)d_in[17];
    const float* outW    = (const float*)d_in[18];
    const float* outb    = (const float*)d_in[19];

    const int MMA_SMEM = 4 * 128 * 72 * 2;   // 73728 B
    static int attr_set = 0;
    if (!attr_set) {
        cudaFuncSetAttribute(mma_kernel, cudaFuncAttributeMaxDynamicSharedMemorySize, MMA_SMEM);
        attr_set = 1;
    }

    prep_kernel<<<126 + 1536 + 625, 256>>>((const unsigned*)p2, ae, embW, embB,
                                           cheFW, cheFb, cheGW, cheGb,
                                           vdwFW, vdwFb, vdwGW, vdwGb);
    table16_kernel<<<dim3(KNOT, 6), 128>>>();

    int src = 0;
    for (int i = 0; i < 3; i++) {
        mma_kernel<<<dim3(157, 8), 256, MMA_SMEM>>>(i);
        conv_kernel<<<NPTS / NBLK, 128>>>(che_fea, (const float*)p2, (const float*)p3,
                                          (const int*)p2, (const int*)p3, vdw_idx, src, i);
        src ^= 1;
    }
    pool_kernel<<<BCRY, 128>>>(natoms, fc1W, fc1b, outW, outb, (float*)d_out, src);
}